// round 1
// baseline (speedup 1.0000x reference)
#include <cuda_runtime.h>
#include <cuda_bf16.h>
#include <math.h>

// Problem constants
#define BATCH 2
#define SEQ   2048
#define TOK   (BATCH*SEQ)      // 4096 tokens
#define DM    1024
#define EDIM  2048
#define NSTATE 16
#define KCONV 4
#define RRANK 64
#define XDBL  (RRANK + 2*NSTATE)   // 96
#define EPSV  1e-5f

// ---------------- scratch (device globals, no allocation) ----------------
__device__ float g_xn  [TOK * DM];        // 16 MB  rmsnorm output
__device__ float g_xz  [TOK * 2 * EDIM];  // 64 MB  in_proj output (u | z)
__device__ float g_uc  [TOK * EDIM];      // 32 MB  conv+silu output
__device__ float g_xdbl[TOK * XDBL];      // 1.5 MB x_proj output (dt_low|B|C)
__device__ float g_dt  [TOK * EDIM];      // 32 MB  softplus(dt)
__device__ float g_y   [TOK * EDIM];      // 32 MB  gated scan output

// ---------------- RMSNorm ----------------
__global__ void rmsnorm_kernel(const float* __restrict__ x,
                               const float* __restrict__ nw,
                               float* __restrict__ xn) {
    int t = blockIdx.x;
    const float* row = x + (size_t)t * DM;
    float ss = 0.f;
    for (int i = threadIdx.x; i < DM; i += 256) {
        float v = row[i];
        ss += v * v;
    }
    // warp reduce
    for (int o = 16; o > 0; o >>= 1) ss += __shfl_xor_sync(0xffffffffu, ss, o);
    __shared__ float sred[8];
    int wid = threadIdx.x >> 5, lid = threadIdx.x & 31;
    if (lid == 0) sred[wid] = ss;
    __syncthreads();
    __shared__ float s_scale;
    if (threadIdx.x == 0) {
        float tot = 0.f;
        #pragma unroll
        for (int i = 0; i < 8; i++) tot += sred[i];
        s_scale = rsqrtf(tot / (float)DM + EPSV);
    }
    __syncthreads();
    float sc = s_scale;
    for (int i = threadIdx.x; i < DM; i += 256)
        xn[(size_t)t * DM + i] = row[i] * sc * nw[i];
}

// ---------------- Tiled SGEMM: C[M,N] = A[M,K] * B[N,K]^T (+ epilogue) ----
// EPI: 0 = plain, 1 = softplus(acc + bias[n]), 2 = acc + resid[m*ldc+n]
template<int BM, int BN, int BK, int TM, int TN, int EPI>
__global__ void gemm_nt_kernel(const float* __restrict__ A,
                               const float* __restrict__ Bw,
                               float* __restrict__ C,
                               int Kd, int lda, int ldb, int ldc,
                               const float* __restrict__ bias,
                               const float* __restrict__ resid) {
    constexpr int THREADS = (BM / TM) * (BN / TN);
    __shared__ float As[BK][BM + 4];
    __shared__ float Bs[BK][BN + 4];
    const int tid = threadIdx.x;
    const int tx = tid % (BN / TN);
    const int ty = tid / (BN / TN);
    const int m0 = blockIdx.y * BM;
    const int n0 = blockIdx.x * BN;

    float acc[TM][TN];
    #pragma unroll
    for (int i = 0; i < TM; i++)
        #pragma unroll
        for (int j = 0; j < TN; j++) acc[i][j] = 0.f;

    for (int k0 = 0; k0 < Kd; k0 += BK) {
        const int A_F4 = BM * BK / 4;
        for (int i = tid; i < A_F4; i += THREADS) {
            int r  = i / (BK / 4);
            int c4 = i % (BK / 4);
            float4 v = *(const float4*)&A[(size_t)(m0 + r) * lda + k0 + c4 * 4];
            As[c4 * 4 + 0][r] = v.x;
            As[c4 * 4 + 1][r] = v.y;
            As[c4 * 4 + 2][r] = v.z;
            As[c4 * 4 + 3][r] = v.w;
        }
        const int B_F4 = BN * BK / 4;
        for (int i = tid; i < B_F4; i += THREADS) {
            int r  = i / (BK / 4);
            int c4 = i % (BK / 4);
            float4 v = *(const float4*)&Bw[(size_t)(n0 + r) * ldb + k0 + c4 * 4];
            Bs[c4 * 4 + 0][r] = v.x;
            Bs[c4 * 4 + 1][r] = v.y;
            Bs[c4 * 4 + 2][r] = v.z;
            Bs[c4 * 4 + 3][r] = v.w;
        }
        __syncthreads();
        #pragma unroll
        for (int kk = 0; kk < BK; kk++) {
            float ra[TM], rb[TN];
            #pragma unroll
            for (int i = 0; i < TM; i++) ra[i] = As[kk][ty * TM + i];
            #pragma unroll
            for (int j = 0; j < TN; j++) rb[j] = Bs[kk][tx * TN + j];
            #pragma unroll
            for (int i = 0; i < TM; i++)
                #pragma unroll
                for (int j = 0; j < TN; j++)
                    acc[i][j] = fmaf(ra[i], rb[j], acc[i][j]);
        }
        __syncthreads();
    }

    #pragma unroll
    for (int i = 0; i < TM; i++) {
        int m = m0 + ty * TM + i;
        #pragma unroll
        for (int j = 0; j < TN; j++) {
            int n = n0 + tx * TN + j;
            float v = acc[i][j];
            if (EPI == 1) {
                v += bias[n];
                v = (v > 20.f) ? v : log1pf(__expf(v));
            } else if (EPI == 2) {
                v += resid[(size_t)m * ldc + n];
            }
            C[(size_t)m * ldc + n] = v;
        }
    }
}

// ---------------- causal depthwise conv (K=4) + SiLU ----------------
__global__ void conv_silu_kernel(const float* __restrict__ xz,
                                 const float* __restrict__ w,
                                 const float* __restrict__ bias,
                                 float* __restrict__ uc) {
    int idx = blockIdx.x * blockDim.x + threadIdx.x;  // t*EDIM + e
    if (idx >= TOK * EDIM) return;
    int e = idx & (EDIM - 1);
    int t = idx >> 11;
    int b = t >> 11;
    int l = t & (SEQ - 1);
    float acc = bias[e];
    #pragma unroll
    for (int j = 0; j < KCONV; j++) {
        int ll = l - (KCONV - 1) + j;
        if (ll >= 0)
            acc = fmaf(xz[(size_t)(b * SEQ + ll) * (2 * EDIM) + e],
                       w[e * KCONV + j], acc);
    }
    uc[idx] = acc / (1.f + __expf(-acc));  // SiLU
}

// ---------------- selective scan: lane-per-(b,e,n), 16 lanes/group --------
// fuses y = (scan + u*D) * silu(z)
__global__ void scan_kernel(const float* __restrict__ dt,
                            const float* __restrict__ u,
                            const float* __restrict__ xz,
                            const float* __restrict__ xdbl,
                            const float* __restrict__ A_log,
                            const float* __restrict__ Dp,
                            float* __restrict__ y) {
    int grp = blockIdx.x * (blockDim.x >> 4) + (threadIdx.x >> 4);  // (b,e)
    int n = threadIdx.x & 15;
    int b = grp >> 11;          // / EDIM
    int e = grp & (EDIM - 1);
    float Aen = -__expf(A_log[e * NSTATE + n]);
    float Dv = Dp[e];
    float h = 0.f;
    const int base_t = b * SEQ;
    for (int l = 0; l < SEQ; ++l) {
        int t = base_t + l;
        float dtv = dt[(size_t)t * EDIM + e];
        float uv  = u [(size_t)t * EDIM + e];
        float Bv  = xdbl[t * XDBL + RRANK + n];
        float Cv  = xdbl[t * XDBL + RRANK + NSTATE + n];
        h = fmaf(h, __expf(dtv * Aen), dtv * uv * Bv);
        float p = h * Cv;
        p += __shfl_xor_sync(0xffffffffu, p, 8);
        p += __shfl_xor_sync(0xffffffffu, p, 4);
        p += __shfl_xor_sync(0xffffffffu, p, 2);
        p += __shfl_xor_sync(0xffffffffu, p, 1);
        if (n == 0) {
            float zv = xz[(size_t)t * (2 * EDIM) + EDIM + e];
            float sz = zv / (1.f + __expf(-zv));
            y[(size_t)t * EDIM + e] = (p + uv * Dv) * sz;
        }
    }
}

// ---------------- launch ----------------
extern "C" void kernel_launch(void* const* d_in, const int* in_sizes, int n_in,
                              void* d_out, int out_size) {
    const float* x         = (const float*)d_in[0];
    const float* norm_w    = (const float*)d_in[1];
    const float* in_proj_w = (const float*)d_in[2];
    const float* conv_w    = (const float*)d_in[3];
    const float* conv_b    = (const float*)d_in[4];
    const float* x_proj_w  = (const float*)d_in[5];
    const float* dt_proj_w = (const float*)d_in[6];
    const float* dt_proj_b = (const float*)d_in[7];
    const float* A_log     = (const float*)d_in[8];
    const float* Dp        = (const float*)d_in[9];
    const float* out_proj_w= (const float*)d_in[10];
    float* out = (float*)d_out;

    float *p_xn, *p_xz, *p_uc, *p_xdbl, *p_dt, *p_y;
    cudaGetSymbolAddress((void**)&p_xn,   g_xn);
    cudaGetSymbolAddress((void**)&p_xz,   g_xz);
    cudaGetSymbolAddress((void**)&p_uc,   g_uc);
    cudaGetSymbolAddress((void**)&p_xdbl, g_xdbl);
    cudaGetSymbolAddress((void**)&p_dt,   g_dt);
    cudaGetSymbolAddress((void**)&p_y,    g_y);

    // 1. RMSNorm
    rmsnorm_kernel<<<TOK, 256>>>(x, norm_w, p_xn);

    // 2. in_proj: [4096,1024] @ [4096,1024]^T -> [4096,4096]
    gemm_nt_kernel<128,128,16,8,8,0><<<dim3(2*EDIM/128, TOK/128), 256>>>(
        p_xn, in_proj_w, p_xz, DM, DM, DM, 2*EDIM, nullptr, nullptr);

    // 3. conv + SiLU
    conv_silu_kernel<<<(TOK*EDIM)/256, 256>>>(p_xz, conv_w, conv_b, p_uc);

    // 4. x_proj: [4096,2048] @ [96,2048]^T -> [4096,96]
    gemm_nt_kernel<128,96,16,8,6,0><<<dim3(1, TOK/128), 256>>>(
        p_uc, x_proj_w, p_xdbl, EDIM, EDIM, EDIM, XDBL, nullptr, nullptr);

    // 5. dt_proj + bias + softplus: [4096,64] @ [2048,64]^T -> [4096,2048]
    gemm_nt_kernel<128,128,16,8,8,1><<<dim3(EDIM/128, TOK/128), 256>>>(
        p_xdbl, dt_proj_w, p_dt, RRANK, XDBL, RRANK, EDIM, dt_proj_b, nullptr);

    // 6. selective scan (+ D skip + z gate)
    scan_kernel<<<(BATCH*EDIM)/8, 128>>>(p_dt, p_uc, p_xz, p_xdbl, A_log, Dp, p_y);

    // 7. out_proj + residual: [4096,2048] @ [1024,2048]^T -> [4096,1024]
    gemm_nt_kernel<128,128,16,8,8,2><<<dim3(DM/128, TOK/128), 256>>>(
        p_y, out_proj_w, out, EDIM, EDIM, EDIM, DM, nullptr, x);
}

// round 2
// speedup vs baseline: 1.3388x; 1.3388x over previous
#include <cuda_runtime.h>
#include <cuda_bf16.h>
#include <math.h>
#include <stdint.h>

// Problem constants
#define BATCH 2
#define SEQ   2048
#define TOK   (BATCH*SEQ)      // 4096 tokens
#define DM    1024
#define EDIM  2048
#define NSTATE 16
#define KCONV 4
#define RRANK 64
#define XDBL  (RRANK + 2*NSTATE)   // 96
#define EPSV  1e-5f

// ---------------- scratch (device globals, no allocation) ----------------
__device__ float g_xn  [TOK * DM];        // rmsnorm output
__device__ float g_xz  [TOK * 2 * EDIM];  // in_proj output (u | z)
__device__ float g_uc  [TOK * EDIM];      // conv+silu output
__device__ float g_xdbl[TOK * XDBL];      // x_proj output (dt_low|B|C)
__device__ float g_dt  [TOK * EDIM];      // softplus(dt)
__device__ float g_y   [TOK * EDIM];      // gated scan output

// bf16 hi/lo splits for tensor-core GEMMs
__device__ __nv_bfloat16 g_xnh[TOK * DM],  g_xnl[TOK * DM];
__device__ __nv_bfloat16 g_wih[2*EDIM*DM], g_wil[2*EDIM*DM];
__device__ __nv_bfloat16 g_yh [TOK * EDIM], g_yl [TOK * EDIM];
__device__ __nv_bfloat16 g_woh[DM * EDIM], g_wol[DM * EDIM];

// ---------------- fp32 -> bf16 hi/lo split ----------------
__global__ void split_kernel(const float* __restrict__ src,
                             __nv_bfloat16* __restrict__ hi,
                             __nv_bfloat16* __restrict__ lo, int n) {
    int i = blockIdx.x * blockDim.x + threadIdx.x;
    if (i >= n) return;
    float v = src[i];
    __nv_bfloat16 h = __float2bfloat16(v);
    hi[i] = h;
    lo[i] = __float2bfloat16(v - __bfloat162float(h));
}

// ---------------- RMSNorm ----------------
__global__ void rmsnorm_kernel(const float* __restrict__ x,
                               const float* __restrict__ nw,
                               float* __restrict__ xn) {
    int t = blockIdx.x;
    const float* row = x + (size_t)t * DM;
    float ss = 0.f;
    for (int i = threadIdx.x; i < DM; i += 256) {
        float v = row[i];
        ss += v * v;
    }
    for (int o = 16; o > 0; o >>= 1) ss += __shfl_xor_sync(0xffffffffu, ss, o);
    __shared__ float sred[8];
    int wid = threadIdx.x >> 5, lid = threadIdx.x & 31;
    if (lid == 0) sred[wid] = ss;
    __syncthreads();
    __shared__ float s_scale;
    if (threadIdx.x == 0) {
        float tot = 0.f;
        #pragma unroll
        for (int i = 0; i < 8; i++) tot += sred[i];
        s_scale = rsqrtf(tot / (float)DM + EPSV);
    }
    __syncthreads();
    float sc = s_scale;
    for (int i = threadIdx.x; i < DM; i += 256)
        xn[(size_t)t * DM + i] = row[i] * sc * nw[i];
}

// ---------------- mma.sync helpers ----------------
__device__ __forceinline__ void ldmx4(uint32_t* r, const void* p) {
    uint32_t a = (uint32_t)__cvta_generic_to_shared(p);
    asm volatile("ldmatrix.sync.aligned.m8n8.x4.shared.b16 {%0,%1,%2,%3}, [%4];\n"
                 : "=r"(r[0]), "=r"(r[1]), "=r"(r[2]), "=r"(r[3]) : "r"(a));
}
__device__ __forceinline__ void mma_bf16(float* d, const uint32_t* a, const uint32_t* b) {
    asm volatile("mma.sync.aligned.m16n8k16.row.col.f32.bf16.bf16.f32 "
                 "{%0,%1,%2,%3}, {%4,%5,%6,%7}, {%8,%9}, {%0,%1,%2,%3};\n"
                 : "+f"(d[0]), "+f"(d[1]), "+f"(d[2]), "+f"(d[3])
                 : "r"(a[0]), "r"(a[1]), "r"(a[2]), "r"(a[3]), "r"(b[0]), "r"(b[1]));
}

// ---------------- bf16 3-split tensor-core GEMM (NT) ----------------
// C[M,N] = A[M,K] * B[N,K]^T with A ~ Ah+Al, B ~ Bh+Bl
// block 128x128, BK=32, 8 warps (2x4), warp tile 64x32
// EPI: 0 = plain, 2 = +resid
template<int EPI>
__global__ void __launch_bounds__(256)
gemm_bf16x3_kernel(const __nv_bfloat16* __restrict__ Ah, const __nv_bfloat16* __restrict__ Al,
                   const __nv_bfloat16* __restrict__ Bh, const __nv_bfloat16* __restrict__ Bl,
                   float* __restrict__ C, int Kd, int ldc,
                   const float* __restrict__ resid) {
    __shared__ __nv_bfloat16 Ash[128][40], Asl[128][40], Bsh[128][40], Bsl[128][40];
    const int tid = threadIdx.x;
    const int lane = tid & 31, warp = tid >> 5;
    const int wm = warp >> 2, wn = warp & 3;           // 2 x 4 warp grid
    const int m0 = blockIdx.y * 128, n0 = blockIdx.x * 128;

    float acc[4][4][4];
    #pragma unroll
    for (int i = 0; i < 4; i++)
        #pragma unroll
        for (int j = 0; j < 4; j++)
            #pragma unroll
            for (int r = 0; r < 4; r++) acc[i][j][r] = 0.f;

    const int a_row  = lane & 15;
    const int a_koff = 8 * (lane >> 4);
    const int b_row  = (lane & 7) + 8 * (lane >> 4);
    const int b_koff = 8 * ((lane >> 3) & 1);

    for (int k0 = 0; k0 < Kd; k0 += 32) {
        __syncthreads();
        #pragma unroll
        for (int i = tid; i < 512; i += 256) {
            int r = i >> 2, c8 = (i & 3) * 8;
            *(uint4*)&Ash[r][c8] = *(const uint4*)&Ah[(size_t)(m0 + r) * Kd + k0 + c8];
            *(uint4*)&Asl[r][c8] = *(const uint4*)&Al[(size_t)(m0 + r) * Kd + k0 + c8];
            *(uint4*)&Bsh[r][c8] = *(const uint4*)&Bh[(size_t)(n0 + r) * Kd + k0 + c8];
            *(uint4*)&Bsl[r][c8] = *(const uint4*)&Bl[(size_t)(n0 + r) * Kd + k0 + c8];
        }
        __syncthreads();
        #pragma unroll
        for (int kk = 0; kk < 32; kk += 16) {
            uint32_t ah[4][4], al[4][4], bh[4][2], bl[4][2];
            #pragma unroll
            for (int mt = 0; mt < 4; mt++) {
                int row = wm * 64 + mt * 16 + a_row;
                ldmx4(ah[mt], &Ash[row][kk + a_koff]);
                ldmx4(al[mt], &Asl[row][kk + a_koff]);
            }
            #pragma unroll
            for (int np = 0; np < 2; np++) {
                int row = wn * 32 + np * 16 + b_row;
                uint32_t t[4];
                ldmx4(t, &Bsh[row][kk + b_koff]);
                bh[2*np][0] = t[0]; bh[2*np][1] = t[1];
                bh[2*np+1][0] = t[2]; bh[2*np+1][1] = t[3];
                ldmx4(t, &Bsl[row][kk + b_koff]);
                bl[2*np][0] = t[0]; bl[2*np][1] = t[1];
                bl[2*np+1][0] = t[2]; bl[2*np+1][1] = t[3];
            }
            #pragma unroll
            for (int mt = 0; mt < 4; mt++)
                #pragma unroll
                for (int nt = 0; nt < 4; nt++) {
                    mma_bf16(acc[mt][nt], ah[mt], bh[nt]);
                    mma_bf16(acc[mt][nt], ah[mt], bl[nt]);
                    mma_bf16(acc[mt][nt], al[mt], bh[nt]);
                }
        }
    }

    const int gr = lane >> 2, gc2 = (lane & 3) * 2;
    #pragma unroll
    for (int mt = 0; mt < 4; mt++) {
        int m = m0 + wm * 64 + mt * 16 + gr;
        #pragma unroll
        for (int nt = 0; nt < 4; nt++) {
            int n = n0 + wn * 32 + nt * 8 + gc2;
            float2 v01 = make_float2(acc[mt][nt][0], acc[mt][nt][1]);
            float2 v23 = make_float2(acc[mt][nt][2], acc[mt][nt][3]);
            if (EPI == 2) {
                const float2 r01 = *(const float2*)&resid[(size_t)m * ldc + n];
                const float2 r23 = *(const float2*)&resid[(size_t)(m + 8) * ldc + n];
                v01.x += r01.x; v01.y += r01.y;
                v23.x += r23.x; v23.y += r23.y;
            }
            *(float2*)&C[(size_t)m * ldc + n] = v01;
            *(float2*)&C[(size_t)(m + 8) * ldc + n] = v23;
        }
    }
}

// ---------------- Tiled SGEMM (small GEMMs): C = A * B^T (+ epilogue) -----
// EPI: 0 = plain, 1 = softplus(acc + bias[n])
template<int BM, int BN, int BK, int TM, int TN, int EPI>
__global__ void gemm_nt_kernel(const float* __restrict__ A,
                               const float* __restrict__ Bw,
                               float* __restrict__ C,
                               int Kd, int lda, int ldb, int ldc,
                               const float* __restrict__ bias) {
    constexpr int THREADS = (BM / TM) * (BN / TN);
    __shared__ float As[BK][BM + 4];
    __shared__ float Bs[BK][BN + 4];
    const int tid = threadIdx.x;
    const int tx = tid % (BN / TN);
    const int ty = tid / (BN / TN);
    const int m0 = blockIdx.y * BM;
    const int n0 = blockIdx.x * BN;

    float acc[TM][TN];
    #pragma unroll
    for (int i = 0; i < TM; i++)
        #pragma unroll
        for (int j = 0; j < TN; j++) acc[i][j] = 0.f;

    for (int k0 = 0; k0 < Kd; k0 += BK) {
        const int A_F4 = BM * BK / 4;
        for (int i = tid; i < A_F4; i += THREADS) {
            int r  = i / (BK / 4);
            int c4 = i % (BK / 4);
            float4 v = *(const float4*)&A[(size_t)(m0 + r) * lda + k0 + c4 * 4];
            As[c4 * 4 + 0][r] = v.x;
            As[c4 * 4 + 1][r] = v.y;
            As[c4 * 4 + 2][r] = v.z;
            As[c4 * 4 + 3][r] = v.w;
        }
        const int B_F4 = BN * BK / 4;
        for (int i = tid; i < B_F4; i += THREADS) {
            int r  = i / (BK / 4);
            int c4 = i % (BK / 4);
            float4 v = *(const float4*)&Bw[(size_t)(n0 + r) * ldb + k0 + c4 * 4];
            Bs[c4 * 4 + 0][r] = v.x;
            Bs[c4 * 4 + 1][r] = v.y;
            Bs[c4 * 4 + 2][r] = v.z;
            Bs[c4 * 4 + 3][r] = v.w;
        }
        __syncthreads();
        #pragma unroll
        for (int kk = 0; kk < BK; kk++) {
            float ra[TM], rb[TN];
            #pragma unroll
            for (int i = 0; i < TM; i++) ra[i] = As[kk][ty * TM + i];
            #pragma unroll
            for (int j = 0; j < TN; j++) rb[j] = Bs[kk][tx * TN + j];
            #pragma unroll
            for (int i = 0; i < TM; i++)
                #pragma unroll
                for (int j = 0; j < TN; j++)
                    acc[i][j] = fmaf(ra[i], rb[j], acc[i][j]);
        }
        __syncthreads();
    }

    #pragma unroll
    for (int i = 0; i < TM; i++) {
        int m = m0 + ty * TM + i;
        #pragma unroll
        for (int j = 0; j < TN; j++) {
            int n = n0 + tx * TN + j;
            float v = acc[i][j];
            if (EPI == 1) {
                v += bias[n];
                v = (v > 20.f) ? v : log1pf(__expf(v));
            }
            C[(size_t)m * ldc + n] = v;
        }
    }
}

// ---------------- causal depthwise conv (K=4) + SiLU ----------------
__global__ void conv_silu_kernel(const float* __restrict__ xz,
                                 const float* __restrict__ w,
                                 const float* __restrict__ bias,
                                 float* __restrict__ uc) {
    int idx = blockIdx.x * blockDim.x + threadIdx.x;  // t*EDIM + e
    if (idx >= TOK * EDIM) return;
    int e = idx & (EDIM - 1);
    int t = idx >> 11;
    int b = t >> 11;
    int l = t & (SEQ - 1);
    float acc = bias[e];
    #pragma unroll
    for (int j = 0; j < KCONV; j++) {
        int ll = l - (KCONV - 1) + j;
        if (ll >= 0)
            acc = fmaf(xz[(size_t)(b * SEQ + ll) * (2 * EDIM) + e],
                       w[e * KCONV + j], acc);
    }
    uc[idx] = acc / (1.f + __expf(-acc));  // SiLU
}

// ---------------- selective scan: lane-per-(b,e,n) ----------------
__global__ void scan_kernel(const float* __restrict__ dt,
                            const float* __restrict__ u,
                            const float* __restrict__ xz,
                            const float* __restrict__ xdbl,
                            const float* __restrict__ A_log,
                            const float* __restrict__ Dp,
                            float* __restrict__ y) {
    int grp = blockIdx.x * (blockDim.x >> 4) + (threadIdx.x >> 4);  // (b,e)
    int n = threadIdx.x & 15;
    int b = grp >> 11;
    int e = grp & (EDIM - 1);
    float Aen = -__expf(A_log[e * NSTATE + n]);
    float Dv = Dp[e];
    float h = 0.f;
    const int base_t = b * SEQ;
    for (int l = 0; l < SEQ; ++l) {
        int t = base_t + l;
        float dtv = dt[(size_t)t * EDIM + e];
        float uv  = u [(size_t)t * EDIM + e];
        float Bv  = xdbl[t * XDBL + RRANK + n];
        float Cv  = xdbl[t * XDBL + RRANK + NSTATE + n];
        h = fmaf(h, __expf(dtv * Aen), dtv * uv * Bv);
        float p = h * Cv;
        p += __shfl_xor_sync(0xffffffffu, p, 8);
        p += __shfl_xor_sync(0xffffffffu, p, 4);
        p += __shfl_xor_sync(0xffffffffu, p, 2);
        p += __shfl_xor_sync(0xffffffffu, p, 1);
        if (n == 0) {
            float zv = xz[(size_t)t * (2 * EDIM) + EDIM + e];
            float sz = zv / (1.f + __expf(-zv));
            y[(size_t)t * EDIM + e] = (p + uv * Dv) * sz;
        }
    }
}

// ---------------- launch ----------------
extern "C" void kernel_launch(void* const* d_in, const int* in_sizes, int n_in,
                              void* d_out, int out_size) {
    const float* x         = (const float*)d_in[0];
    const float* norm_w    = (const float*)d_in[1];
    const float* in_proj_w = (const float*)d_in[2];
    const float* conv_w    = (const float*)d_in[3];
    const float* conv_b    = (const float*)d_in[4];
    const float* x_proj_w  = (const float*)d_in[5];
    const float* dt_proj_w = (const float*)d_in[6];
    const float* dt_proj_b = (const float*)d_in[7];
    const float* A_log     = (const float*)d_in[8];
    const float* Dp        = (const float*)d_in[9];
    const float* out_proj_w= (const float*)d_in[10];
    float* out = (float*)d_out;

    float *p_xn, *p_xz, *p_uc, *p_xdbl, *p_dt, *p_y;
    cudaGetSymbolAddress((void**)&p_xn,   g_xn);
    cudaGetSymbolAddress((void**)&p_xz,   g_xz);
    cudaGetSymbolAddress((void**)&p_uc,   g_uc);
    cudaGetSymbolAddress((void**)&p_xdbl, g_xdbl);
    cudaGetSymbolAddress((void**)&p_dt,   g_dt);
    cudaGetSymbolAddress((void**)&p_y,    g_y);
    __nv_bfloat16 *p_xnh, *p_xnl, *p_wih, *p_wil, *p_yh, *p_yl, *p_woh, *p_wol;
    cudaGetSymbolAddress((void**)&p_xnh, g_xnh);
    cudaGetSymbolAddress((void**)&p_xnl, g_xnl);
    cudaGetSymbolAddress((void**)&p_wih, g_wih);
    cudaGetSymbolAddress((void**)&p_wil, g_wil);
    cudaGetSymbolAddress((void**)&p_yh,  g_yh);
    cudaGetSymbolAddress((void**)&p_yl,  g_yl);
    cudaGetSymbolAddress((void**)&p_woh, g_woh);
    cudaGetSymbolAddress((void**)&p_wol, g_wol);

    // 1. RMSNorm
    rmsnorm_kernel<<<TOK, 256>>>(x, norm_w, p_xn);

    // 2. split xn and in_proj_w to bf16 hi/lo
    split_kernel<<<(TOK*DM + 255)/256, 256>>>(p_xn, p_xnh, p_xnl, TOK*DM);
    split_kernel<<<(2*EDIM*DM + 255)/256, 256>>>(in_proj_w, p_wih, p_wil, 2*EDIM*DM);

    // 3. in_proj (tensor cores): [4096,1024] @ [4096,1024]^T -> [4096,4096]
    gemm_bf16x3_kernel<0><<<dim3(2*EDIM/128, TOK/128), 256>>>(
        p_xnh, p_xnl, p_wih, p_wil, p_xz, DM, 2*EDIM, nullptr);

    // 4. conv + SiLU
    conv_silu_kernel<<<(TOK*EDIM)/256, 256>>>(p_xz, conv_w, conv_b, p_uc);

    // 5. x_proj: [4096,2048] @ [96,2048]^T -> [4096,96]  (small tiles, 128 blocks)
    gemm_nt_kernel<32,96,32,4,6,0><<<dim3(1, TOK/32), 128>>>(
        p_uc, x_proj_w, p_xdbl, EDIM, EDIM, EDIM, XDBL, nullptr);

    // 6. dt_proj + bias + softplus: [4096,64] @ [2048,64]^T -> [4096,2048]
    gemm_nt_kernel<128,128,16,8,8,1><<<dim3(EDIM/128, TOK/128), 256>>>(
        p_xdbl, dt_proj_w, p_dt, RRANK, XDBL, RRANK, EDIM, dt_proj_b);

    // 7. selective scan (+ D skip + z gate)
    scan_kernel<<<(BATCH*EDIM)/8, 128>>>(p_dt, p_uc, p_xz, p_xdbl, A_log, Dp, p_y);

    // 8. split y and out_proj_w
    split_kernel<<<(TOK*EDIM + 255)/256, 256>>>(p_y, p_yh, p_yl, TOK*EDIM);
    split_kernel<<<(DM*EDIM + 255)/256, 256>>>(out_proj_w, p_woh, p_wol, DM*EDIM);

    // 9. out_proj + residual (tensor cores): [4096,2048] @ [1024,2048]^T -> [4096,1024]
    gemm_bf16x3_kernel<2><<<dim3(DM/128, TOK/128), 256>>>(
        p_yh, p_yl, p_woh, p_wol, out, EDIM, DM, x);
}

// round 3
// speedup vs baseline: 2.3725x; 1.7721x over previous
#include <cuda_runtime.h>
#include <cuda_bf16.h>
#include <math.h>
#include <stdint.h>

// Problem constants
#define BATCH 2
#define SEQ   2048
#define TOK   (BATCH*SEQ)      // 4096 tokens
#define DM    1024
#define EDIM  2048
#define NSTATE 16
#define KCONV 4
#define RRANK 64
#define XDBL  (RRANK + 2*NSTATE)   // 96
#define EPSV  1e-5f
#define NCHUNK 32
#define CLEN   64              // NCHUNK*CLEN = SEQ

// ---------------- scratch (device globals, no allocation) ----------------
__device__ float g_xz  [TOK * 2 * EDIM];  // in_proj output (u | z)
__device__ float g_uc  [TOK * EDIM];      // conv+silu output
__device__ float g_xdbl[TOK * XDBL];      // x_proj output (dt_low|B|C)
__device__ float g_dt  [TOK * EDIM];      // softplus(dt)
__device__ float g_hloc  [BATCH*EDIM*NCHUNK*NSTATE];
__device__ float g_hstart[BATCH*EDIM*NCHUNK*NSTATE];
__device__ float g_ssum  [BATCH*EDIM*NCHUNK];

// bf16 hi/lo splits for tensor-core GEMMs
__device__ __nv_bfloat16 g_xnh[TOK * DM],  g_xnl[TOK * DM];
__device__ __nv_bfloat16 g_wih[2*EDIM*DM], g_wil[2*EDIM*DM];
__device__ __nv_bfloat16 g_yh [TOK * EDIM], g_yl [TOK * EDIM];
__device__ __nv_bfloat16 g_woh[DM * EDIM], g_wol[DM * EDIM];

// ---------------- fp32 -> bf16 hi/lo split ----------------
__global__ void split_kernel(const float* __restrict__ src,
                             __nv_bfloat16* __restrict__ hi,
                             __nv_bfloat16* __restrict__ lo, int n) {
    int i = blockIdx.x * blockDim.x + threadIdx.x;
    if (i >= n) return;
    float v = src[i];
    __nv_bfloat16 h = __float2bfloat16(v);
    hi[i] = h;
    lo[i] = __float2bfloat16(v - __bfloat162float(h));
}

// ---------------- RMSNorm fused with bf16 hi/lo split ----------------
__global__ void rmsnorm_split_kernel(const float* __restrict__ x,
                                     const float* __restrict__ nw,
                                     __nv_bfloat16* __restrict__ xnh,
                                     __nv_bfloat16* __restrict__ xnl) {
    int t = blockIdx.x;
    const float* row = x + (size_t)t * DM;
    float ss = 0.f;
    for (int i = threadIdx.x; i < DM; i += 256) {
        float v = row[i];
        ss += v * v;
    }
    for (int o = 16; o > 0; o >>= 1) ss += __shfl_xor_sync(0xffffffffu, ss, o);
    __shared__ float sred[8];
    int wid = threadIdx.x >> 5, lid = threadIdx.x & 31;
    if (lid == 0) sred[wid] = ss;
    __syncthreads();
    __shared__ float s_scale;
    if (threadIdx.x == 0) {
        float tot = 0.f;
        #pragma unroll
        for (int i = 0; i < 8; i++) tot += sred[i];
        s_scale = rsqrtf(tot / (float)DM + EPSV);
    }
    __syncthreads();
    float sc = s_scale;
    for (int i = threadIdx.x; i < DM; i += 256) {
        float v = row[i] * sc * nw[i];
        __nv_bfloat16 h = __float2bfloat16(v);
        xnh[(size_t)t * DM + i] = h;
        xnl[(size_t)t * DM + i] = __float2bfloat16(v - __bfloat162float(h));
    }
}

// ---------------- mma.sync helpers ----------------
__device__ __forceinline__ void ldmx4(uint32_t* r, const void* p) {
    uint32_t a = (uint32_t)__cvta_generic_to_shared(p);
    asm volatile("ldmatrix.sync.aligned.m8n8.x4.shared.b16 {%0,%1,%2,%3}, [%4];\n"
                 : "=r"(r[0]), "=r"(r[1]), "=r"(r[2]), "=r"(r[3]) : "r"(a));
}
__device__ __forceinline__ void mma_bf16(float* d, const uint32_t* a, const uint32_t* b) {
    asm volatile("mma.sync.aligned.m16n8k16.row.col.f32.bf16.bf16.f32 "
                 "{%0,%1,%2,%3}, {%4,%5,%6,%7}, {%8,%9}, {%0,%1,%2,%3};\n"
                 : "+f"(d[0]), "+f"(d[1]), "+f"(d[2]), "+f"(d[3])
                 : "r"(a[0]), "r"(a[1]), "r"(a[2]), "r"(a[3]), "r"(b[0]), "r"(b[1]));
}
__device__ __forceinline__ void cpa16(void* dst, const void* src) {
    uint32_t d = (uint32_t)__cvta_generic_to_shared(dst);
    asm volatile("cp.async.cg.shared.global [%0], [%1], 16;\n" :: "r"(d), "l"(src));
}

// ---------------- bf16 3-split tensor-core GEMM, 2-stage cp.async --------
// C[M,N] = A[M,K] * B[N,K]^T with A ~ Ah+Al, B ~ Bh+Bl
// block 128x128, BK=32, 8 warps (2x4), warp tile 64x32
// EPI: 0 = plain, 2 = +resid
// dynamic smem: 2 stages x 4 buffers x 128 x 40 bf16 = 81920 B
#define BUFSZ 5120
template<int EPI>
__global__ void __launch_bounds__(256, 2)
gemm_bf16x3_pipe(const __nv_bfloat16* __restrict__ Ah, const __nv_bfloat16* __restrict__ Al,
                 const __nv_bfloat16* __restrict__ Bh, const __nv_bfloat16* __restrict__ Bl,
                 float* __restrict__ C, int Kd, int ldc,
                 const float* __restrict__ resid) {
    extern __shared__ __nv_bfloat16 smp[];
    const int tid = threadIdx.x;
    const int lane = tid & 31, warp = tid >> 5;
    const int wm = warp >> 2, wn = warp & 3;
    const int m0 = blockIdx.y * 128, n0 = blockIdx.x * 128;

    const __nv_bfloat16* srcA[4] = {Ah + (size_t)m0 * Kd, Al + (size_t)m0 * Kd,
                                    Bh + (size_t)n0 * Kd, Bl + (size_t)n0 * Kd};

    float acc[4][4][4];
    #pragma unroll
    for (int i = 0; i < 4; i++)
        #pragma unroll
        for (int j = 0; j < 4; j++)
            #pragma unroll
            for (int r = 0; r < 4; r++) acc[i][j][r] = 0.f;

    const int a_row  = lane & 15;
    const int a_koff = 8 * (lane >> 4);
    const int b_row  = (lane & 7) + 8 * (lane >> 4);
    const int b_koff = 8 * ((lane >> 3) & 1);

    // per-thread copy assignments: 2 chunks per buffer
    const int r0c = tid >> 2, c0c = (tid & 3) * 8;          // i = tid
    const int r1c = (tid + 256) >> 2, c1c = ((tid + 256) & 3) * 8;

    auto issue = [&](int st, int k0) {
        __nv_bfloat16* base = smp + st * 4 * BUFSZ;
        #pragma unroll
        for (int bidx = 0; bidx < 4; bidx++) {
            __nv_bfloat16* dst = base + bidx * BUFSZ;
            const __nv_bfloat16* s = srcA[bidx] + k0;
            cpa16(dst + r0c * 40 + c0c, s + (size_t)r0c * Kd + c0c);
            cpa16(dst + r1c * 40 + c1c, s + (size_t)r1c * Kd + c1c);
        }
    };

    issue(0, 0);
    asm volatile("cp.async.commit_group;\n");
    const int KT = Kd >> 5;
    for (int kt = 0; kt < KT; kt++) {
        if (kt + 1 < KT) {
            issue((kt + 1) & 1, (kt + 1) << 5);
            asm volatile("cp.async.commit_group;\n");
            asm volatile("cp.async.wait_group 1;\n");
        } else {
            asm volatile("cp.async.wait_group 0;\n");
        }
        __syncthreads();
        __nv_bfloat16* base = smp + (kt & 1) * 4 * BUFSZ;
        __nv_bfloat16* Ash = base;
        __nv_bfloat16* Asl = base + BUFSZ;
        __nv_bfloat16* Bsh = base + 2 * BUFSZ;
        __nv_bfloat16* Bsl = base + 3 * BUFSZ;
        #pragma unroll
        for (int kk = 0; kk < 32; kk += 16) {
            uint32_t ah[4][4], al[4][4], bh[4][2], bl[4][2];
            #pragma unroll
            for (int mt = 0; mt < 4; mt++) {
                int row = wm * 64 + mt * 16 + a_row;
                ldmx4(ah[mt], Ash + row * 40 + kk + a_koff);
                ldmx4(al[mt], Asl + row * 40 + kk + a_koff);
            }
            #pragma unroll
            for (int np = 0; np < 2; np++) {
                int row = wn * 32 + np * 16 + b_row;
                uint32_t t[4];
                ldmx4(t, Bsh + row * 40 + kk + b_koff);
                bh[2*np][0] = t[0]; bh[2*np][1] = t[1];
                bh[2*np+1][0] = t[2]; bh[2*np+1][1] = t[3];
                ldmx4(t, Bsl + row * 40 + kk + b_koff);
                bl[2*np][0] = t[0]; bl[2*np][1] = t[1];
                bl[2*np+1][0] = t[2]; bl[2*np+1][1] = t[3];
            }
            #pragma unroll
            for (int mt = 0; mt < 4; mt++)
                #pragma unroll
                for (int nt = 0; nt < 4; nt++) {
                    mma_bf16(acc[mt][nt], ah[mt], bh[nt]);
                    mma_bf16(acc[mt][nt], ah[mt], bl[nt]);
                    mma_bf16(acc[mt][nt], al[mt], bh[nt]);
                }
        }
        __syncthreads();
    }

    const int gr = lane >> 2, gc2 = (lane & 3) * 2;
    #pragma unroll
    for (int mt = 0; mt < 4; mt++) {
        int m = m0 + wm * 64 + mt * 16 + gr;
        #pragma unroll
        for (int nt = 0; nt < 4; nt++) {
            int n = n0 + wn * 32 + nt * 8 + gc2;
            float2 v01 = make_float2(acc[mt][nt][0], acc[mt][nt][1]);
            float2 v23 = make_float2(acc[mt][nt][2], acc[mt][nt][3]);
            if (EPI == 2) {
                const float2 r01 = *(const float2*)&resid[(size_t)m * ldc + n];
                const float2 r23 = *(const float2*)&resid[(size_t)(m + 8) * ldc + n];
                v01.x += r01.x; v01.y += r01.y;
                v23.x += r23.x; v23.y += r23.y;
            }
            *(float2*)&C[(size_t)m * ldc + n] = v01;
            *(float2*)&C[(size_t)(m + 8) * ldc + n] = v23;
        }
    }
}

// ---------------- Tiled SGEMM (small GEMMs): C = A * B^T (+ epilogue) -----
// EPI: 0 = plain, 1 = softplus(acc + bias[n])
template<int BM, int BN, int BK, int TM, int TN, int EPI>
__global__ void gemm_nt_kernel(const float* __restrict__ A,
                               const float* __restrict__ Bw,
                               float* __restrict__ C,
                               int Kd, int lda, int ldb, int ldc,
                               const float* __restrict__ bias) {
    constexpr int THREADS = (BM / TM) * (BN / TN);
    __shared__ float As[BK][BM + 4];
    __shared__ float Bs[BK][BN + 4];
    const int tid = threadIdx.x;
    const int tx = tid % (BN / TN);
    const int ty = tid / (BN / TN);
    const int m0 = blockIdx.y * BM;
    const int n0 = blockIdx.x * BN;

    float acc[TM][TN];
    #pragma unroll
    for (int i = 0; i < TM; i++)
        #pragma unroll
        for (int j = 0; j < TN; j++) acc[i][j] = 0.f;

    for (int k0 = 0; k0 < Kd; k0 += BK) {
        const int A_F4 = BM * BK / 4;
        for (int i = tid; i < A_F4; i += THREADS) {
            int r  = i / (BK / 4);
            int c4 = i % (BK / 4);
            float4 v = *(const float4*)&A[(size_t)(m0 + r) * lda + k0 + c4 * 4];
            As[c4 * 4 + 0][r] = v.x;
            As[c4 * 4 + 1][r] = v.y;
            As[c4 * 4 + 2][r] = v.z;
            As[c4 * 4 + 3][r] = v.w;
        }
        const int B_F4 = BN * BK / 4;
        for (int i = tid; i < B_F4; i += THREADS) {
            int r  = i / (BK / 4);
            int c4 = i % (BK / 4);
            float4 v = *(const float4*)&Bw[(size_t)(n0 + r) * ldb + k0 + c4 * 4];
            Bs[c4 * 4 + 0][r] = v.x;
            Bs[c4 * 4 + 1][r] = v.y;
            Bs[c4 * 4 + 2][r] = v.z;
            Bs[c4 * 4 + 3][r] = v.w;
        }
        __syncthreads();
        #pragma unroll
        for (int kk = 0; kk < BK; kk++) {
            float ra[TM], rb[TN];
            #pragma unroll
            for (int i = 0; i < TM; i++) ra[i] = As[kk][ty * TM + i];
            #pragma unroll
            for (int j = 0; j < TN; j++) rb[j] = Bs[kk][tx * TN + j];
            #pragma unroll
            for (int i = 0; i < TM; i++)
                #pragma unroll
                for (int j = 0; j < TN; j++)
                    acc[i][j] = fmaf(ra[i], rb[j], acc[i][j]);
        }
        __syncthreads();
    }

    #pragma unroll
    for (int i = 0; i < TM; i++) {
        int m = m0 + ty * TM + i;
        #pragma unroll
        for (int j = 0; j < TN; j++) {
            int n = n0 + tx * TN + j;
            float v = acc[i][j];
            if (EPI == 1) {
                v += bias[n];
                v = (v > 20.f) ? v : log1pf(__expf(v));
            }
            C[(size_t)m * ldc + n] = v;
        }
    }
}

// ---------------- causal depthwise conv (K=4) + SiLU ----------------
__global__ void conv_silu_kernel(const float* __restrict__ xz,
                                 const float* __restrict__ w,
                                 const float* __restrict__ bias,
                                 float* __restrict__ uc) {
    int idx = blockIdx.x * blockDim.x + threadIdx.x;  // t*EDIM + e
    if (idx >= TOK * EDIM) return;
    int e = idx & (EDIM - 1);
    int t = idx >> 11;
    int b = t >> 11;
    int l = t & (SEQ - 1);
    float acc = bias[e];
    #pragma unroll
    for (int j = 0; j < KCONV; j++) {
        int ll = l - (KCONV - 1) + j;
        if (ll >= 0)
            acc = fmaf(xz[(size_t)(b * SEQ + ll) * (2 * EDIM) + e],
                       w[e * KCONV + j], acc);
    }
    uc[idx] = acc / (1.f + __expf(-acc));  // SiLU
}

// ---------------- chunked selective scan ----------------
// pass1: per (b,e,chunk,n) lane, compute local h (h0=0) and sum(dt)
__global__ void scan_pass1(const float* __restrict__ dt,
                           const float* __restrict__ u,
                           const float* __restrict__ xdbl,
                           const float* __restrict__ A_log,
                           float* __restrict__ hloc,
                           float* __restrict__ ssum) {
    int g = blockIdx.x * 16 + (threadIdx.x >> 4);   // (b,e,c)
    int n = threadIdx.x & 15;
    int c = g & (NCHUNK - 1);
    int e = (g >> 5) & (EDIM - 1);
    int b = g >> 16;
    float Aen = -__expf(A_log[e * NSTATE + n]);
    float h = 0.f, s = 0.f;
    int t0 = b * SEQ + c * CLEN;
    for (int l = 0; l < CLEN; l++) {
        int t = t0 + l;
        float dtv = dt[(size_t)t * EDIM + e];
        float uv  = u [(size_t)t * EDIM + e];
        float Bv  = xdbl[t * XDBL + RRANK + n];
        s += dtv;
        h = fmaf(h, __expf(dtv * Aen), dtv * uv * Bv);
    }
    hloc[(size_t)g * NSTATE + n] = h;
    if (n == 0) ssum[g] = s;
}

// pass2: per (b,e,n), sequentially combine chunks -> per-chunk start state
__global__ void scan_pass2(const float* __restrict__ A_log,
                           const float* __restrict__ ssum,
                           const float* __restrict__ hloc,
                           float* __restrict__ hstart) {
    int i = blockIdx.x * 256 + threadIdx.x;
    int n = i & 15;
    int e = (i >> 4) & (EDIM - 1);
    int b = i >> 15;
    float Aen = -__expf(A_log[e * NSTATE + n]);
    float h = 0.f;
    int gbase = (b * EDIM + e) * NCHUNK;
    for (int c = 0; c < NCHUNK; c++) {
        int g = gbase + c;
        hstart[(size_t)g * NSTATE + n] = h;
        h = fmaf(h, __expf(Aen * ssum[g]), hloc[(size_t)g * NSTATE + n]);
    }
}

// pass3: replay with correct start state, emit gated y as bf16 hi/lo
__global__ void scan_pass3(const float* __restrict__ dt,
                           const float* __restrict__ u,
                           const float* __restrict__ xz,
                           const float* __restrict__ xdbl,
                           const float* __restrict__ A_log,
                           const float* __restrict__ Dp,
                           const float* __restrict__ hstart,
                           __nv_bfloat16* __restrict__ yh,
                           __nv_bfloat16* __restrict__ yl) {
    int g = blockIdx.x * 16 + (threadIdx.x >> 4);
    int n = threadIdx.x & 15;
    int c = g & (NCHUNK - 1);
    int e = (g >> 5) & (EDIM - 1);
    int b = g >> 16;
    float Aen = -__expf(A_log[e * NSTATE + n]);
    float Dv = Dp[e];
    float h = hstart[(size_t)g * NSTATE + n];
    int t0 = b * SEQ + c * CLEN;
    for (int l = 0; l < CLEN; l++) {
        int t = t0 + l;
        float dtv = dt[(size_t)t * EDIM + e];
        float uv  = u [(size_t)t * EDIM + e];
        float Bv  = xdbl[t * XDBL + RRANK + n];
        float Cv  = xdbl[t * XDBL + RRANK + NSTATE + n];
        h = fmaf(h, __expf(dtv * Aen), dtv * uv * Bv);
        float p = h * Cv;
        p += __shfl_xor_sync(0xffffffffu, p, 8);
        p += __shfl_xor_sync(0xffffffffu, p, 4);
        p += __shfl_xor_sync(0xffffffffu, p, 2);
        p += __shfl_xor_sync(0xffffffffu, p, 1);
        if (n == 0) {
            float zv = xz[(size_t)t * (2 * EDIM) + EDIM + e];
            float sz = zv / (1.f + __expf(-zv));
            float yv = (p + uv * Dv) * sz;
            __nv_bfloat16 hb = __float2bfloat16(yv);
            yh[(size_t)t * EDIM + e] = hb;
            yl[(size_t)t * EDIM + e] = __float2bfloat16(yv - __bfloat162float(hb));
        }
    }
}

// ---------------- launch ----------------
extern "C" void kernel_launch(void* const* d_in, const int* in_sizes, int n_in,
                              void* d_out, int out_size) {
    const float* x         = (const float*)d_in[0];
    const float* norm_w    = (const float*)d_in[1];
    const float* in_proj_w = (const float*)d_in[2];
    const float* conv_w    = (const float*)d_in[3];
    const float* conv_b    = (const float*)d_in[4];
    const float* x_proj_w  = (const float*)d_in[5];
    const float* dt_proj_w = (const float*)d_in[6];
    const float* dt_proj_b = (const float*)d_in[7];
    const float* A_log     = (const float*)d_in[8];
    const float* Dp        = (const float*)d_in[9];
    const float* out_proj_w= (const float*)d_in[10];
    float* out = (float*)d_out;

    float *p_xz, *p_uc, *p_xdbl, *p_dt, *p_hloc, *p_hstart, *p_ssum;
    cudaGetSymbolAddress((void**)&p_xz,    g_xz);
    cudaGetSymbolAddress((void**)&p_uc,    g_uc);
    cudaGetSymbolAddress((void**)&p_xdbl,  g_xdbl);
    cudaGetSymbolAddress((void**)&p_dt,    g_dt);
    cudaGetSymbolAddress((void**)&p_hloc,  g_hloc);
    cudaGetSymbolAddress((void**)&p_hstart,g_hstart);
    cudaGetSymbolAddress((void**)&p_ssum,  g_ssum);
    __nv_bfloat16 *p_xnh, *p_xnl, *p_wih, *p_wil, *p_yh, *p_yl, *p_woh, *p_wol;
    cudaGetSymbolAddress((void**)&p_xnh, g_xnh);
    cudaGetSymbolAddress((void**)&p_xnl, g_xnl);
    cudaGetSymbolAddress((void**)&p_wih, g_wih);
    cudaGetSymbolAddress((void**)&p_wil, g_wil);
    cudaGetSymbolAddress((void**)&p_yh,  g_yh);
    cudaGetSymbolAddress((void**)&p_yl,  g_yl);
    cudaGetSymbolAddress((void**)&p_woh, g_woh);
    cudaGetSymbolAddress((void**)&p_wol, g_wol);

    const int SMEM_PIPE = 2 * 4 * BUFSZ * (int)sizeof(__nv_bfloat16);  // 81920
    cudaFuncSetAttribute(gemm_bf16x3_pipe<0>,
                         cudaFuncAttributeMaxDynamicSharedMemorySize, SMEM_PIPE);
    cudaFuncSetAttribute(gemm_bf16x3_pipe<2>,
                         cudaFuncAttributeMaxDynamicSharedMemorySize, SMEM_PIPE);

    // 1. RMSNorm fused with bf16 split
    rmsnorm_split_kernel<<<TOK, 256>>>(x, norm_w, p_xnh, p_xnl);

    // 2-3. weight splits (independent, run early)
    split_kernel<<<(2*EDIM*DM + 255)/256, 256>>>(in_proj_w, p_wih, p_wil, 2*EDIM*DM);
    split_kernel<<<(DM*EDIM + 255)/256, 256>>>(out_proj_w, p_woh, p_wol, DM*EDIM);

    // 4. in_proj (tensor cores, pipelined): [4096,1024]@[4096,1024]^T -> [4096,4096]
    gemm_bf16x3_pipe<0><<<dim3(2*EDIM/128, TOK/128), 256, SMEM_PIPE>>>(
        p_xnh, p_xnl, p_wih, p_wil, p_xz, DM, 2*EDIM, nullptr);

    // 5. conv + SiLU
    conv_silu_kernel<<<(TOK*EDIM)/256, 256>>>(p_xz, conv_w, conv_b, p_uc);

    // 6. x_proj: [4096,2048] @ [96,2048]^T -> [4096,96]
    gemm_nt_kernel<32,96,32,4,6,0><<<dim3(1, TOK/32), 128>>>(
        p_uc, x_proj_w, p_xdbl, EDIM, EDIM, EDIM, XDBL, nullptr);

    // 7. dt_proj + bias + softplus: [4096,64] @ [2048,64]^T -> [4096,2048]
    gemm_nt_kernel<128,128,16,8,8,1><<<dim3(EDIM/128, TOK/128), 256>>>(
        p_xdbl, dt_proj_w, p_dt, RRANK, XDBL, RRANK, EDIM, dt_proj_b);

    // 8-10. chunked selective scan (+ D skip + z gate + bf16 split)
    scan_pass1<<<BATCH*EDIM*NCHUNK/16, 256>>>(p_dt, p_uc, p_xdbl, A_log, p_hloc, p_ssum);
    scan_pass2<<<BATCH*EDIM*NSTATE/256, 256>>>(A_log, p_ssum, p_hloc, p_hstart);
    scan_pass3<<<BATCH*EDIM*NCHUNK/16, 256>>>(p_dt, p_uc, p_xz, p_xdbl, A_log, Dp,
                                              p_hstart, p_yh, p_yl);

    // 11. out_proj + residual (tensor cores): [4096,2048]@[1024,2048]^T -> [4096,1024]
    gemm_bf16x3_pipe<2><<<dim3(DM/128, TOK/128), 256, SMEM_PIPE>>>(
        p_yh, p_yl, p_woh, p_wol, out, EDIM, DM, x);
}

// round 5
// speedup vs baseline: 2.6907x; 1.1341x over previous
#include <cuda_runtime.h>
#include <cuda_bf16.h>
#include <math.h>
#include <stdint.h>

// Problem constants
#define BATCH 2
#define SEQ   2048
#define TOK   (BATCH*SEQ)      // 4096 tokens
#define DM    1024
#define EDIM  2048
#define NSTATE 16
#define KCONV 4
#define RRANK 64
#define XDBL  (RRANK + 2*NSTATE)   // 96
#define EPSV  1e-5f
#define NCHUNK 32
#define CLEN   64              // NCHUNK*CLEN = SEQ

// ---------------- scratch (device globals, no allocation) ----------------
__device__ float g_xz  [TOK * 2 * EDIM];  // in_proj output (u | z)
__device__ float g_uc  [TOK * EDIM];      // conv+silu output
__device__ float g_xdbl[TOK * XDBL];      // x_proj output (dt_low|B|C)
__device__ float g_dt  [TOK * EDIM];      // softplus(dt)
__device__ float g_hloc  [BATCH*EDIM*NCHUNK*NSTATE];
__device__ float g_hstart[BATCH*EDIM*NCHUNK*NSTATE];
__device__ float g_ssum  [BATCH*EDIM*NCHUNK];

// bf16 hi/lo splits for tensor-core GEMMs
__device__ __nv_bfloat16 g_xnh[TOK * DM],  g_xnl[TOK * DM];
__device__ __nv_bfloat16 g_wih[2*EDIM*DM], g_wil[2*EDIM*DM];
__device__ __nv_bfloat16 g_yh [TOK * EDIM], g_yl [TOK * EDIM];
__device__ __nv_bfloat16 g_woh[DM * EDIM], g_wol[DM * EDIM];

// ---------------- fp32 -> bf16 hi/lo split ----------------
__global__ void split_kernel(const float* __restrict__ src,
                             __nv_bfloat16* __restrict__ hi,
                             __nv_bfloat16* __restrict__ lo, int n) {
    int i = blockIdx.x * blockDim.x + threadIdx.x;
    if (i >= n) return;
    float v = src[i];
    __nv_bfloat16 h = __float2bfloat16(v);
    hi[i] = h;
    lo[i] = __float2bfloat16(v - __bfloat162float(h));
}

// ---------------- RMSNorm fused with bf16 hi/lo split ----------------
__global__ void rmsnorm_split_kernel(const float* __restrict__ x,
                                     const float* __restrict__ nw,
                                     __nv_bfloat16* __restrict__ xnh,
                                     __nv_bfloat16* __restrict__ xnl) {
    int t = blockIdx.x;
    const float* row = x + (size_t)t * DM;
    float ss = 0.f;
    for (int i = threadIdx.x; i < DM; i += 256) {
        float v = row[i];
        ss += v * v;
    }
    for (int o = 16; o > 0; o >>= 1) ss += __shfl_xor_sync(0xffffffffu, ss, o);
    __shared__ float sred[8];
    int wid = threadIdx.x >> 5, lid = threadIdx.x & 31;
    if (lid == 0) sred[wid] = ss;
    __syncthreads();
    __shared__ float s_scale;
    if (threadIdx.x == 0) {
        float tot = 0.f;
        #pragma unroll
        for (int i = 0; i < 8; i++) tot += sred[i];
        s_scale = rsqrtf(tot / (float)DM + EPSV);
    }
    __syncthreads();
    float sc = s_scale;
    for (int i = threadIdx.x; i < DM; i += 256) {
        float v = row[i] * sc * nw[i];
        __nv_bfloat16 h = __float2bfloat16(v);
        xnh[(size_t)t * DM + i] = h;
        xnl[(size_t)t * DM + i] = __float2bfloat16(v - __bfloat162float(h));
    }
}

// ---------------- mma.sync helpers ----------------
__device__ __forceinline__ void ldmx4(uint32_t* r, const void* p) {
    uint32_t a = (uint32_t)__cvta_generic_to_shared(p);
    asm volatile("ldmatrix.sync.aligned.m8n8.x4.shared.b16 {%0,%1,%2,%3}, [%4];\n"
                 : "=r"(r[0]), "=r"(r[1]), "=r"(r[2]), "=r"(r[3]) : "r"(a));
}
__device__ __forceinline__ void mma_bf16(float* d, const uint32_t* a, const uint32_t* b) {
    asm volatile("mma.sync.aligned.m16n8k16.row.col.f32.bf16.bf16.f32 "
                 "{%0,%1,%2,%3}, {%4,%5,%6,%7}, {%8,%9}, {%0,%1,%2,%3};\n"
                 : "+f"(d[0]), "+f"(d[1]), "+f"(d[2]), "+f"(d[3])
                 : "r"(a[0]), "r"(a[1]), "r"(a[2]), "r"(a[3]), "r"(b[0]), "r"(b[1]));
}
__device__ __forceinline__ void cpa16(void* dst, const void* src) {
    uint32_t d = (uint32_t)__cvta_generic_to_shared(dst);
    asm volatile("cp.async.cg.shared.global [%0], [%1], 16;\n" :: "r"(d), "l"(src));
}

// ---------------- bf16 3-split tensor-core GEMM, 2-stage cp.async --------
// C[M,N] = A[M,K] * B[N,K]^T with A ~ Ah+Al, B ~ Bh+Bl
// block 128x128, BK=32, 8 warps (2x4), warp tile 64x32
// EPI: 0 = plain, 2 = +resid
#define BUFSZ 5120
template<int EPI>
__global__ void __launch_bounds__(256, 2)
gemm_bf16x3_pipe(const __nv_bfloat16* __restrict__ Ah, const __nv_bfloat16* __restrict__ Al,
                 const __nv_bfloat16* __restrict__ Bh, const __nv_bfloat16* __restrict__ Bl,
                 float* __restrict__ C, int Kd, int ldc,
                 const float* __restrict__ resid) {
    extern __shared__ __nv_bfloat16 smp[];
    const int tid = threadIdx.x;
    const int lane = tid & 31, warp = tid >> 5;
    const int wm = warp >> 2, wn = warp & 3;
    const int m0 = blockIdx.y * 128, n0 = blockIdx.x * 128;

    const __nv_bfloat16* srcA[4] = {Ah + (size_t)m0 * Kd, Al + (size_t)m0 * Kd,
                                    Bh + (size_t)n0 * Kd, Bl + (size_t)n0 * Kd};

    float acc[4][4][4];
    #pragma unroll
    for (int i = 0; i < 4; i++)
        #pragma unroll
        for (int j = 0; j < 4; j++)
            #pragma unroll
            for (int r = 0; r < 4; r++) acc[i][j][r] = 0.f;

    const int a_row  = lane & 15;
    const int a_koff = 8 * (lane >> 4);
    const int b_row  = (lane & 7) + 8 * (lane >> 4);
    const int b_koff = 8 * ((lane >> 3) & 1);

    const int r0c = tid >> 2, c0c = (tid & 3) * 8;
    const int r1c = (tid + 256) >> 2, c1c = ((tid + 256) & 3) * 8;

    auto issue = [&](int st, int k0) {
        __nv_bfloat16* base = smp + st * 4 * BUFSZ;
        #pragma unroll
        for (int bidx = 0; bidx < 4; bidx++) {
            __nv_bfloat16* dst = base + bidx * BUFSZ;
            const __nv_bfloat16* s = srcA[bidx] + k0;
            cpa16(dst + r0c * 40 + c0c, s + (size_t)r0c * Kd + c0c);
            cpa16(dst + r1c * 40 + c1c, s + (size_t)r1c * Kd + c1c);
        }
    };

    issue(0, 0);
    asm volatile("cp.async.commit_group;\n");
    const int KT = Kd >> 5;
    for (int kt = 0; kt < KT; kt++) {
        if (kt + 1 < KT) {
            issue((kt + 1) & 1, (kt + 1) << 5);
            asm volatile("cp.async.commit_group;\n");
            asm volatile("cp.async.wait_group 1;\n");
        } else {
            asm volatile("cp.async.wait_group 0;\n");
        }
        __syncthreads();
        __nv_bfloat16* base = smp + (kt & 1) * 4 * BUFSZ;
        __nv_bfloat16* Ash = base;
        __nv_bfloat16* Asl = base + BUFSZ;
        __nv_bfloat16* Bsh = base + 2 * BUFSZ;
        __nv_bfloat16* Bsl = base + 3 * BUFSZ;
        #pragma unroll
        for (int kk = 0; kk < 32; kk += 16) {
            uint32_t ah[4][4], al[4][4], bh[4][2], bl[4][2];
            #pragma unroll
            for (int mt = 0; mt < 4; mt++) {
                int row = wm * 64 + mt * 16 + a_row;
                ldmx4(ah[mt], Ash + row * 40 + kk + a_koff);
                ldmx4(al[mt], Asl + row * 40 + kk + a_koff);
            }
            #pragma unroll
            for (int np = 0; np < 2; np++) {
                int row = wn * 32 + np * 16 + b_row;
                uint32_t t[4];
                ldmx4(t, Bsh + row * 40 + kk + b_koff);
                bh[2*np][0] = t[0]; bh[2*np][1] = t[1];
                bh[2*np+1][0] = t[2]; bh[2*np+1][1] = t[3];
                ldmx4(t, Bsl + row * 40 + kk + b_koff);
                bl[2*np][0] = t[0]; bl[2*np][1] = t[1];
                bl[2*np+1][0] = t[2]; bl[2*np+1][1] = t[3];
            }
            #pragma unroll
            for (int mt = 0; mt < 4; mt++)
                #pragma unroll
                for (int nt = 0; nt < 4; nt++) {
                    mma_bf16(acc[mt][nt], ah[mt], bh[nt]);
                    mma_bf16(acc[mt][nt], ah[mt], bl[nt]);
                    mma_bf16(acc[mt][nt], al[mt], bh[nt]);
                }
        }
        __syncthreads();
    }

    const int gr = lane >> 2, gc2 = (lane & 3) * 2;
    #pragma unroll
    for (int mt = 0; mt < 4; mt++) {
        int m = m0 + wm * 64 + mt * 16 + gr;
        #pragma unroll
        for (int nt = 0; nt < 4; nt++) {
            int n = n0 + wn * 32 + nt * 8 + gc2;
            float2 v01 = make_float2(acc[mt][nt][0], acc[mt][nt][1]);
            float2 v23 = make_float2(acc[mt][nt][2], acc[mt][nt][3]);
            if (EPI == 2) {
                const float2 r01 = *(const float2*)&resid[(size_t)m * ldc + n];
                const float2 r23 = *(const float2*)&resid[(size_t)(m + 8) * ldc + n];
                v01.x += r01.x; v01.y += r01.y;
                v23.x += r23.x; v23.y += r23.y;
            }
            *(float2*)&C[(size_t)m * ldc + n] = v01;
            *(float2*)&C[(size_t)(m + 8) * ldc + n] = v23;
        }
    }
}

// ---------------- Tiled SGEMM (small GEMMs): C = A * B^T (+ epilogue) -----
// EPI: 0 = plain, 1 = softplus(acc + bias[n])
template<int BM, int BN, int BK, int TM, int TN, int EPI>
__global__ void gemm_nt_kernel(const float* __restrict__ A,
                               const float* __restrict__ Bw,
                               float* __restrict__ C,
                               int Kd, int lda, int ldb, int ldc,
                               const float* __restrict__ bias) {
    constexpr int THREADS = (BM / TM) * (BN / TN);
    __shared__ float As[BK][BM + 4];
    __shared__ float Bs[BK][BN + 4];
    const int tid = threadIdx.x;
    const int tx = tid % (BN / TN);
    const int ty = tid / (BN / TN);
    const int m0 = blockIdx.y * BM;
    const int n0 = blockIdx.x * BN;

    float acc[TM][TN];
    #pragma unroll
    for (int i = 0; i < TM; i++)
        #pragma unroll
        for (int j = 0; j < TN; j++) acc[i][j] = 0.f;

    for (int k0 = 0; k0 < Kd; k0 += BK) {
        const int A_F4 = BM * BK / 4;
        for (int i = tid; i < A_F4; i += THREADS) {
            int r  = i / (BK / 4);
            int c4 = i % (BK / 4);
            float4 v = *(const float4*)&A[(size_t)(m0 + r) * lda + k0 + c4 * 4];
            As[c4 * 4 + 0][r] = v.x;
            As[c4 * 4 + 1][r] = v.y;
            As[c4 * 4 + 2][r] = v.z;
            As[c4 * 4 + 3][r] = v.w;
        }
        const int B_F4 = BN * BK / 4;
        for (int i = tid; i < B_F4; i += THREADS) {
            int r  = i / (BK / 4);
            int c4 = i % (BK / 4);
            float4 v = *(const float4*)&Bw[(size_t)(n0 + r) * ldb + k0 + c4 * 4];
            Bs[c4 * 4 + 0][r] = v.x;
            Bs[c4 * 4 + 1][r] = v.y;
            Bs[c4 * 4 + 2][r] = v.z;
            Bs[c4 * 4 + 3][r] = v.w;
        }
        __syncthreads();
        #pragma unroll
        for (int kk = 0; kk < BK; kk++) {
            float ra[TM], rb[TN];
            #pragma unroll
            for (int i = 0; i < TM; i++) ra[i] = As[kk][ty * TM + i];
            #pragma unroll
            for (int j = 0; j < TN; j++) rb[j] = Bs[kk][tx * TN + j];
            #pragma unroll
            for (int i = 0; i < TM; i++)
                #pragma unroll
                for (int j = 0; j < TN; j++)
                    acc[i][j] = fmaf(ra[i], rb[j], acc[i][j]);
        }
        __syncthreads();
    }

    #pragma unroll
    for (int i = 0; i < TM; i++) {
        int m = m0 + ty * TM + i;
        #pragma unroll
        for (int j = 0; j < TN; j++) {
            int n = n0 + tx * TN + j;
            float v = acc[i][j];
            if (EPI == 1) {
                v += bias[n];
                v = (v > 20.f) ? v : log1pf(__expf(v));
            }
            C[(size_t)m * ldc + n] = v;
        }
    }
}

// ---------------- causal depthwise conv (K=4) + SiLU ----------------
__global__ void conv_silu_kernel(const float* __restrict__ xz,
                                 const float* __restrict__ w,
                                 const float* __restrict__ bias,
                                 float* __restrict__ uc) {
    int idx = blockIdx.x * blockDim.x + threadIdx.x;  // t*EDIM + e
    if (idx >= TOK * EDIM) return;
    int e = idx & (EDIM - 1);
    int t = idx >> 11;
    int b = t >> 11;
    int l = t & (SEQ - 1);
    float acc = bias[e];
    #pragma unroll
    for (int j = 0; j < KCONV; j++) {
        int ll = l - (KCONV - 1) + j;
        if (ll >= 0)
            acc = fmaf(xz[(size_t)(b * SEQ + ll) * (2 * EDIM) + e],
                       w[e * KCONV + j], acc);
    }
    uc[idx] = acc / (1.f + __expf(-acc));  // SiLU
}

// ---------------- chunked selective scan, thread-per-(b,c,e) --------------
// pass1: all 16 states in registers; coalesced dt/u; B staged in smem
__global__ void __launch_bounds__(256) scan_pass1(
        const float* __restrict__ dt,
        const float* __restrict__ u,
        const float* __restrict__ xdbl,
        const float* __restrict__ A_log,
        float* __restrict__ hloc,
        float* __restrict__ ssum) {
    const int e = blockIdx.x * 256 + threadIdx.x;
    const int c = blockIdx.y, b = blockIdx.z;
    __shared__ float4 sB[CLEN][NSTATE/4];
    const int t0 = b * SEQ + c * CLEN;
    for (int i = threadIdx.x; i < CLEN * NSTATE / 4; i += 256) {
        int l = i / (NSTATE/4), q = i % (NSTATE/4);
        sB[l][q] = *(const float4*)&xdbl[(size_t)(t0 + l) * XDBL + RRANK + q * 4];
    }
    __syncthreads();
    float Aen[NSTATE];
    #pragma unroll
    for (int q = 0; q < 4; q++) {
        float4 a = *(const float4*)&A_log[e * NSTATE + q * 4];
        Aen[q*4+0] = -__expf(a.x); Aen[q*4+1] = -__expf(a.y);
        Aen[q*4+2] = -__expf(a.z); Aen[q*4+3] = -__expf(a.w);
    }
    float h[NSTATE];
    #pragma unroll
    for (int n = 0; n < NSTATE; n++) h[n] = 0.f;
    float s = 0.f;
    for (int l = 0; l < CLEN; l++) {
        int t = t0 + l;
        float dtv = dt[(size_t)t * EDIM + e];
        float uv  = u [(size_t)t * EDIM + e];
        s += dtv;
        float du = dtv * uv;
        #pragma unroll
        for (int q = 0; q < 4; q++) {
            float4 Bv = sB[l][q];
            h[q*4+0] = fmaf(h[q*4+0], __expf(dtv * Aen[q*4+0]), du * Bv.x);
            h[q*4+1] = fmaf(h[q*4+1], __expf(dtv * Aen[q*4+1]), du * Bv.y);
            h[q*4+2] = fmaf(h[q*4+2], __expf(dtv * Aen[q*4+2]), du * Bv.z);
            h[q*4+3] = fmaf(h[q*4+3], __expf(dtv * Aen[q*4+3]), du * Bv.w);
        }
    }
    size_t g = ((size_t)(b * EDIM + e) * NCHUNK + c);
    #pragma unroll
    for (int q = 0; q < 4; q++)
        *(float4*)&hloc[g * NSTATE + q * 4] =
            make_float4(h[q*4+0], h[q*4+1], h[q*4+2], h[q*4+3]);
    ssum[g] = s;
}

// pass2: per (b,e,n), sequentially combine chunks -> per-chunk start state
__global__ void scan_pass2(const float* __restrict__ A_log,
                           const float* __restrict__ ssum,
                           const float* __restrict__ hloc,
                           float* __restrict__ hstart) {
    int i = blockIdx.x * 256 + threadIdx.x;
    int n = i & 15;
    int e = (i >> 4) & (EDIM - 1);
    int b = i >> 15;
    float Aen = -__expf(A_log[e * NSTATE + n]);
    float h = 0.f;
    int gbase = (b * EDIM + e) * NCHUNK;
    for (int c = 0; c < NCHUNK; c++) {
        int g = gbase + c;
        hstart[(size_t)g * NSTATE + n] = h;
        h = fmaf(h, __expf(Aen * ssum[g]), hloc[(size_t)g * NSTATE + n]);
    }
}

// pass3: replay with start state; in-register C-dot; emit gated y bf16 hi/lo
__global__ void __launch_bounds__(256) scan_pass3(
        const float* __restrict__ dt,
        const float* __restrict__ u,
        const float* __restrict__ xz,
        const float* __restrict__ xdbl,
        const float* __restrict__ A_log,
        const float* __restrict__ Dp,
        const float* __restrict__ hstart,
        __nv_bfloat16* __restrict__ yh,
        __nv_bfloat16* __restrict__ yl) {
    const int e = blockIdx.x * 256 + threadIdx.x;
    const int c = blockIdx.y, b = blockIdx.z;
    __shared__ float4 sB[CLEN][NSTATE/4];
    __shared__ float4 sC[CLEN][NSTATE/4];
    const int t0 = b * SEQ + c * CLEN;
    for (int i = threadIdx.x; i < CLEN * NSTATE / 4; i += 256) {
        int l = i / (NSTATE/4), q = i % (NSTATE/4);
        sB[l][q] = *(const float4*)&xdbl[(size_t)(t0 + l) * XDBL + RRANK + q * 4];
        sC[l][q] = *(const float4*)&xdbl[(size_t)(t0 + l) * XDBL + RRANK + NSTATE + q * 4];
    }
    __syncthreads();
    float Aen[NSTATE];
    #pragma unroll
    for (int q = 0; q < 4; q++) {
        float4 a = *(const float4*)&A_log[e * NSTATE + q * 4];
        Aen[q*4+0] = -__expf(a.x); Aen[q*4+1] = -__expf(a.y);
        Aen[q*4+2] = -__expf(a.z); Aen[q*4+3] = -__expf(a.w);
    }
    const float Dv = Dp[e];
    size_t g = ((size_t)(b * EDIM + e) * NCHUNK + c);
    float h[NSTATE];
    #pragma unroll
    for (int q = 0; q < 4; q++) {
        float4 v = *(const float4*)&hstart[g * NSTATE + q * 4];
        h[q*4+0] = v.x; h[q*4+1] = v.y; h[q*4+2] = v.z; h[q*4+3] = v.w;
    }
    for (int l = 0; l < CLEN; l++) {
        int t = t0 + l;
        float dtv = dt[(size_t)t * EDIM + e];
        float uv  = u [(size_t)t * EDIM + e];
        float du = dtv * uv;
        float p = 0.f;
        #pragma unroll
        for (int q = 0; q < 4; q++) {
            float4 Bv = sB[l][q];
            float4 Cv = sC[l][q];
            h[q*4+0] = fmaf(h[q*4+0], __expf(dtv * Aen[q*4+0]), du * Bv.x);
            h[q*4+1] = fmaf(h[q*4+1], __expf(dtv * Aen[q*4+1]), du * Bv.y);
            h[q*4+2] = fmaf(h[q*4+2], __expf(dtv * Aen[q*4+2]), du * Bv.z);
            h[q*4+3] = fmaf(h[q*4+3], __expf(dtv * Aen[q*4+3]), du * Bv.w);
            p = fmaf(h[q*4+0], Cv.x, p);
            p = fmaf(h[q*4+1], Cv.y, p);
            p = fmaf(h[q*4+2], Cv.z, p);
            p = fmaf(h[q*4+3], Cv.w, p);
        }
        float zv = xz[(size_t)t * (2 * EDIM) + EDIM + e];
        float sz = zv / (1.f + __expf(-zv));
        float yv = (p + uv * Dv) * sz;
        __nv_bfloat16 hb = __float2bfloat16(yv);
        yh[(size_t)t * EDIM + e] = hb;
        yl[(size_t)t * EDIM + e] = __float2bfloat16(yv - __bfloat162float(hb));
    }
}

// ---------------- launch ----------------
extern "C" void kernel_launch(void* const* d_in, const int* in_sizes, int n_in,
                              void* d_out, int out_size) {
    const float* x         = (const float*)d_in[0];
    const float* norm_w    = (const float*)d_in[1];
    const float* in_proj_w = (const float*)d_in[2];
    const float* conv_w    = (const float*)d_in[3];
    const float* conv_b    = (const float*)d_in[4];
    const float* x_proj_w  = (const float*)d_in[5];
    const float* dt_proj_w = (const float*)d_in[6];
    const float* dt_proj_b = (const float*)d_in[7];
    const float* A_log     = (const float*)d_in[8];
    const float* Dp        = (const float*)d_in[9];
    const float* out_proj_w= (const float*)d_in[10];
    float* out = (float*)d_out;

    float *p_xz, *p_uc, *p_xdbl, *p_dt, *p_hloc, *p_hstart, *p_ssum;
    cudaGetSymbolAddress((void**)&p_xz,    g_xz);
    cudaGetSymbolAddress((void**)&p_uc,    g_uc);
    cudaGetSymbolAddress((void**)&p_xdbl,  g_xdbl);
    cudaGetSymbolAddress((void**)&p_dt,    g_dt);
    cudaGetSymbolAddress((void**)&p_hloc,  g_hloc);
    cudaGetSymbolAddress((void**)&p_hstart,g_hstart);
    cudaGetSymbolAddress((void**)&p_ssum,  g_ssum);
    __nv_bfloat16 *p_xnh, *p_xnl, *p_wih, *p_wil, *p_yh, *p_yl, *p_woh, *p_wol;
    cudaGetSymbolAddress((void**)&p_xnh, g_xnh);
    cudaGetSymbolAddress((void**)&p_xnl, g_xnl);
    cudaGetSymbolAddress((void**)&p_wih, g_wih);
    cudaGetSymbolAddress((void**)&p_wil, g_wil);
    cudaGetSymbolAddress((void**)&p_yh,  g_yh);
    cudaGetSymbolAddress((void**)&p_yl,  g_yl);
    cudaGetSymbolAddress((void**)&p_woh, g_woh);
    cudaGetSymbolAddress((void**)&p_wol, g_wol);

    const int SMEM_PIPE = 2 * 4 * BUFSZ * (int)sizeof(__nv_bfloat16);  // 81920
    cudaFuncSetAttribute(gemm_bf16x3_pipe<0>,
                         cudaFuncAttributeMaxDynamicSharedMemorySize, SMEM_PIPE);
    cudaFuncSetAttribute(gemm_bf16x3_pipe<2>,
                         cudaFuncAttributeMaxDynamicSharedMemorySize, SMEM_PIPE);

    // 1. RMSNorm fused with bf16 split
    rmsnorm_split_kernel<<<TOK, 256>>>(x, norm_w, p_xnh, p_xnl);

    // 2-3. weight splits (independent, run early)
    split_kernel<<<(2*EDIM*DM + 255)/256, 256>>>(in_proj_w, p_wih, p_wil, 2*EDIM*DM);
    split_kernel<<<(DM*EDIM + 255)/256, 256>>>(out_proj_w, p_woh, p_wol, DM*EDIM);

    // 4. in_proj (tensor cores, pipelined): [4096,1024]@[4096,1024]^T -> [4096,4096]
    gemm_bf16x3_pipe<0><<<dim3(2*EDIM/128, TOK/128), 256, SMEM_PIPE>>>(
        p_xnh, p_xnl, p_wih, p_wil, p_xz, DM, 2*EDIM, nullptr);

    // 5. conv + SiLU
    conv_silu_kernel<<<(TOK*EDIM)/256, 256>>>(p_xz, conv_w, conv_b, p_uc);

    // 6. x_proj: [4096,2048] @ [96,2048]^T -> [4096,96]
    gemm_nt_kernel<32,96,32,4,6,0><<<dim3(1, TOK/32), 128>>>(
        p_uc, x_proj_w, p_xdbl, EDIM, EDIM, EDIM, XDBL, nullptr);

    // 7. dt_proj + bias + softplus: [4096,64] @ [2048,64]^T -> [4096,2048]
    gemm_nt_kernel<128,128,16,8,8,1><<<dim3(EDIM/128, TOK/128), 256>>>(
        p_xdbl, dt_proj_w, p_dt, RRANK, XDBL, RRANK, EDIM, dt_proj_b);

    // 8-10. chunked selective scan (+ D skip + z gate + bf16 split)
    scan_pass1<<<dim3(EDIM/256, NCHUNK, BATCH), 256>>>(
        p_dt, p_uc, p_xdbl, A_log, p_hloc, p_ssum);
    scan_pass2<<<BATCH*EDIM*NSTATE/256, 256>>>(A_log, p_ssum, p_hloc, p_hstart);
    scan_pass3<<<dim3(EDIM/256, NCHUNK, BATCH), 256>>>(
        p_dt, p_uc, p_xz, p_xdbl, A_log, Dp, p_hstart, p_yh, p_yl);

    // 11. out_proj + residual (tensor cores): [4096,2048]@[1024,2048]^T -> [4096,1024]
    gemm_bf16x3_pipe<2><<<dim3(DM/128, TOK/128), 256, SMEM_PIPE>>>(
        p_yh, p_yl, p_woh, p_wol, out, EDIM, DM, x);
}

// round 8
// speedup vs baseline: 4.0606x; 1.5091x over previous
#include <cuda_runtime.h>
#include <cuda_bf16.h>
#include <math.h>
#include <stdint.h>

// Problem constants
#define BATCH 2
#define SEQ   2048
#define TOK   (BATCH*SEQ)      // 4096 tokens
#define DM    1024
#define EDIM  2048
#define NSTATE 16
#define KCONV 4
#define RRANK 64
#define XDBL  (RRANK + 2*NSTATE)   // 96
#define EPSV  1e-5f
#define NCHUNK 32
#define CLEN   64              // NCHUNK*CLEN = SEQ

// ---------------- scratch (device globals, no allocation) ----------------
__device__ float g_xz  [TOK * 2 * EDIM];  // in_proj output (u | z)
__device__ float g_uc  [TOK * EDIM];      // conv+silu output
__device__ float g_xdbl[TOK * XDBL];      // x_proj output (dt_low|B|C)
__device__ float g_dt  [TOK * EDIM];      // softplus(dt)
__device__ float g_hloc  [BATCH*EDIM*NCHUNK*NSTATE];
__device__ float g_hstart[BATCH*EDIM*NCHUNK*NSTATE];
__device__ float g_ssum  [BATCH*EDIM*NCHUNK];

// bf16 hi/lo splits for tensor-core GEMMs
__device__ __nv_bfloat16 g_xnh[TOK * DM],  g_xnl[TOK * DM];
__device__ __nv_bfloat16 g_wih[2*EDIM*DM], g_wil[2*EDIM*DM];
__device__ __nv_bfloat16 g_yh [TOK * EDIM], g_yl [TOK * EDIM];
__device__ __nv_bfloat16 g_woh[DM * EDIM], g_wol[DM * EDIM];

// ---------------- helpers ----------------
__device__ __forceinline__ uint32_t smem_u32(const void* p) {
    uint32_t a;
    asm("{ .reg .u64 t; cvta.to.shared.u64 t, %1; cvt.u32.u64 %0, t; }" : "=r"(a) : "l"(p));
    return a;
}
__device__ __forceinline__ void ldmx4u(uint32_t* r, uint32_t a) {
    asm volatile("ldmatrix.sync.aligned.m8n8.x4.shared.b16 {%0,%1,%2,%3}, [%4];\n"
                 : "=r"(r[0]), "=r"(r[1]), "=r"(r[2]), "=r"(r[3]) : "r"(a));
}
__device__ __forceinline__ void mma_bf16(float* d, const uint32_t* a, const uint32_t* b) {
    asm volatile("mma.sync.aligned.m16n8k16.row.col.f32.bf16.bf16.f32 "
                 "{%0,%1,%2,%3}, {%4,%5,%6,%7}, {%8,%9}, {%0,%1,%2,%3};\n"
                 : "+f"(d[0]), "+f"(d[1]), "+f"(d[2]), "+f"(d[3])
                 : "r"(a[0]), "r"(a[1]), "r"(a[2]), "r"(a[3]), "r"(b[0]), "r"(b[1]));
}
__device__ __forceinline__ void cpa16u(uint32_t dst, const void* src) {
    asm volatile("cp.async.cg.shared.global [%0], [%1], 16;\n" :: "r"(dst), "l"(src));
}

// ---------------- fp32 -> bf16 hi/lo split ----------------
__global__ void split_kernel(const float* __restrict__ src,
                             __nv_bfloat16* __restrict__ hi,
                             __nv_bfloat16* __restrict__ lo, int n) {
    int i = blockIdx.x * blockDim.x + threadIdx.x;
    if (i >= n) return;
    float v = src[i];
    __nv_bfloat16 h = __float2bfloat16(v);
    hi[i] = h;
    lo[i] = __float2bfloat16(v - __bfloat162float(h));
}

// ---------------- RMSNorm fused with bf16 hi/lo split ----------------
__global__ void rmsnorm_split_kernel(const float* __restrict__ x,
                                     const float* __restrict__ nw,
                                     __nv_bfloat16* __restrict__ xnh,
                                     __nv_bfloat16* __restrict__ xnl) {
    int t = blockIdx.x;
    const float* row = x + (size_t)t * DM;
    float ss = 0.f;
    for (int i = threadIdx.x; i < DM; i += 256) {
        float v = row[i];
        ss += v * v;
    }
    for (int o = 16; o > 0; o >>= 1) ss += __shfl_xor_sync(0xffffffffu, ss, o);
    __shared__ float sred[8];
    int wid = threadIdx.x >> 5, lid = threadIdx.x & 31;
    if (lid == 0) sred[wid] = ss;
    __syncthreads();
    __shared__ float s_scale;
    if (threadIdx.x == 0) {
        float tot = 0.f;
        #pragma unroll
        for (int i = 0; i < 8; i++) tot += sred[i];
        s_scale = rsqrtf(tot / (float)DM + EPSV);
    }
    __syncthreads();
    float sc = s_scale;
    for (int i = threadIdx.x; i < DM; i += 256) {
        float v = row[i] * sc * nw[i];
        __nv_bfloat16 h = __float2bfloat16(v);
        xnh[(size_t)t * DM + i] = h;
        xnl[(size_t)t * DM + i] = __float2bfloat16(v - __bfloat162float(h));
    }
}

// ---------------- bf16 3-split tensor-core GEMM, 4-stage BK=16 -----------
// C[M,N] = A[M,K]*B[N,K]^T with A~Ah+Al, B~Bh+Bl.
// block 128x128, 8 warps (2x4), warp tile 64x32, lookahead 2 chunks,
// single __syncthreads per chunk.
// Row stride 48B (16 cols data + 8 pad): conflict-free ldmatrix.
// EPI: 0 = plain, 2 = +resid
#define ROWB 48
#define BUF_B (128*ROWB)       // 6144 per matrix per stage
#define STAGE_B (4*BUF_B)      // 24576
#define NSTAGE 4
template<int EPI>
__global__ void __launch_bounds__(256, 2)
gemm_bf16x3_pipe(const __nv_bfloat16* __restrict__ Ah, const __nv_bfloat16* __restrict__ Al,
                 const __nv_bfloat16* __restrict__ Bh, const __nv_bfloat16* __restrict__ Bl,
                 float* __restrict__ C, int Kd, int ldc,
                 const float* __restrict__ resid) {
    extern __shared__ char dsm[];
    const uint32_t dbase = smem_u32(dsm);
    const int tid = threadIdx.x;
    const int lane = tid & 31, warp = tid >> 5;
    const int wm = warp >> 2, wn = warp & 3;
    const int m0 = blockIdx.y * 128, n0 = blockIdx.x * 128;

    const __nv_bfloat16* src[4] = {Ah + (size_t)m0 * Kd, Al + (size_t)m0 * Kd,
                                   Bh + (size_t)n0 * Kd, Bl + (size_t)n0 * Kd};

    float acc[4][4][4];
    #pragma unroll
    for (int i = 0; i < 4; i++)
        #pragma unroll
        for (int j = 0; j < 4; j++)
            #pragma unroll
            for (int r = 0; r < 4; r++) acc[i][j][r] = 0.f;

    // per-thread load map: 1024 16B chunks/stage, 4 per thread
    // idx -> buf = idx>>8, i = idx&255, r = i>>1, j = i&1
    const int i0 = tid * 1;  // idx = tid + it*256

    auto issue = [&](int k0, int st) {
        uint32_t sb = dbase + st * STAGE_B;
        #pragma unroll
        for (int it = 0; it < 4; it++) {
            int idx = tid + it * 256;
            int buf = idx >> 8;
            int i = idx & 255;
            int r = i >> 1, j = i & 1;
            cpa16u(sb + buf * BUF_B + r * ROWB + j * 16,
                   src[buf] + (size_t)r * Kd + k0 + j * 8);
        }
        asm volatile("cp.async.commit_group;\n");
    };

    const int KT = Kd >> 4;   // chunks of 16
    issue(0, 0);
    issue(16, 1);

    // ldsm address components (bytes)
    const uint32_t a_off = (uint32_t)((wm * 64 + (lane & 15)) * ROWB + (lane >> 4) * 16);
    const uint32_t b_off = (uint32_t)((wn * 32 + (lane & 7) + 8 * (lane >> 4)) * ROWB
                                      + ((lane >> 3) & 1) * 16);

    for (int kt = 0; kt < KT; kt++) {
        if (kt + 2 < KT) {
            issue((kt + 2) << 4, (kt + 2) & 3);
            asm volatile("cp.async.wait_group 2;\n");
        } else if (kt + 1 < KT) {
            asm volatile("cp.async.wait_group 1;\n");
        } else {
            asm volatile("cp.async.wait_group 0;\n");
        }
        __syncthreads();

        uint32_t sb = dbase + (kt & 3) * STAGE_B;
        uint32_t ah[4][4], al[4][4], bh[4][2], bl[4][2];
        #pragma unroll
        for (int mt = 0; mt < 4; mt++) {
            ldmx4u(ah[mt], sb + a_off + mt * 16 * ROWB);
            ldmx4u(al[mt], sb + BUF_B + a_off + mt * 16 * ROWB);
        }
        #pragma unroll
        for (int np = 0; np < 2; np++) {
            uint32_t t[4];
            ldmx4u(t, sb + 2 * BUF_B + b_off + np * 16 * ROWB);
            bh[2*np][0] = t[0]; bh[2*np][1] = t[1];
            bh[2*np+1][0] = t[2]; bh[2*np+1][1] = t[3];
            ldmx4u(t, sb + 3 * BUF_B + b_off + np * 16 * ROWB);
            bl[2*np][0] = t[0]; bl[2*np][1] = t[1];
            bl[2*np+1][0] = t[2]; bl[2*np+1][1] = t[3];
        }
        #pragma unroll
        for (int mt = 0; mt < 4; mt++)
            #pragma unroll
            for (int nt = 0; nt < 4; nt++) {
                mma_bf16(acc[mt][nt], ah[mt], bh[nt]);
                mma_bf16(acc[mt][nt], ah[mt], bl[nt]);
                mma_bf16(acc[mt][nt], al[mt], bh[nt]);
            }
    }

    const int gr = lane >> 2, gc2 = (lane & 3) * 2;
    #pragma unroll
    for (int mt = 0; mt < 4; mt++) {
        int m = m0 + wm * 64 + mt * 16 + gr;
        #pragma unroll
        for (int nt = 0; nt < 4; nt++) {
            int n = n0 + wn * 32 + nt * 8 + gc2;
            float2 v01 = make_float2(acc[mt][nt][0], acc[mt][nt][1]);
            float2 v23 = make_float2(acc[mt][nt][2], acc[mt][nt][3]);
            if (EPI == 2) {
                const float2 r01 = *(const float2*)&resid[(size_t)m * ldc + n];
                const float2 r23 = *(const float2*)&resid[(size_t)(m + 8) * ldc + n];
                v01.x += r01.x; v01.y += r01.y;
                v23.x += r23.x; v23.y += r23.y;
            }
            *(float2*)&C[(size_t)m * ldc + n] = v01;
            *(float2*)&C[(size_t)(m + 8) * ldc + n] = v23;
        }
    }
}

// ---------------- Tiled SGEMM (small GEMMs): C = A * B^T (+ epilogue) -----
// EPI: 0 = plain, 1 = softplus(acc + bias[n])
template<int BM, int BN, int BK, int TM, int TN, int EPI>
__global__ void gemm_nt_kernel(const float* __restrict__ A,
                               const float* __restrict__ Bw,
                               float* __restrict__ C,
                               int Kd, int lda, int ldb, int ldc,
                               const float* __restrict__ bias) {
    constexpr int THREADS = (BM / TM) * (BN / TN);
    __shared__ float As[BK][BM + 4];
    __shared__ float Bs[BK][BN + 4];
    const int tid = threadIdx.x;
    const int tx = tid % (BN / TN);
    const int ty = tid / (BN / TN);
    const int m0 = blockIdx.y * BM;
    const int n0 = blockIdx.x * BN;

    float acc[TM][TN];
    #pragma unroll
    for (int i = 0; i < TM; i++)
        #pragma unroll
        for (int j = 0; j < TN; j++) acc[i][j] = 0.f;

    for (int k0 = 0; k0 < Kd; k0 += BK) {
        const int A_F4 = BM * BK / 4;
        for (int i = tid; i < A_F4; i += THREADS) {
            int r  = i / (BK / 4);
            int c4 = i % (BK / 4);
            float4 v = *(const float4*)&A[(size_t)(m0 + r) * lda + k0 + c4 * 4];
            As[c4 * 4 + 0][r] = v.x;
            As[c4 * 4 + 1][r] = v.y;
            As[c4 * 4 + 2][r] = v.z;
            As[c4 * 4 + 3][r] = v.w;
        }
        const int B_F4 = BN * BK / 4;
        for (int i = tid; i < B_F4; i += THREADS) {
            int r  = i / (BK / 4);
            int c4 = i % (BK / 4);
            float4 v = *(const float4*)&Bw[(size_t)(n0 + r) * ldb + k0 + c4 * 4];
            Bs[c4 * 4 + 0][r] = v.x;
            Bs[c4 * 4 + 1][r] = v.y;
            Bs[c4 * 4 + 2][r] = v.z;
            Bs[c4 * 4 + 3][r] = v.w;
        }
        __syncthreads();
        #pragma unroll
        for (int kk = 0; kk < BK; kk++) {
            float ra[TM], rb[TN];
            #pragma unroll
            for (int i = 0; i < TM; i++) ra[i] = As[kk][ty * TM + i];
            #pragma unroll
            for (int j = 0; j < TN; j++) rb[j] = Bs[kk][tx * TN + j];
            #pragma unroll
            for (int i = 0; i < TM; i++)
                #pragma unroll
                for (int j = 0; j < TN; j++)
                    acc[i][j] = fmaf(ra[i], rb[j], acc[i][j]);
        }
        __syncthreads();
    }

    #pragma unroll
    for (int i = 0; i < TM; i++) {
        int m = m0 + ty * TM + i;
        #pragma unroll
        for (int j = 0; j < TN; j++) {
            int n = n0 + tx * TN + j;
            float v = acc[i][j];
            if (EPI == 1) {
                v += bias[n];
                v = (v > 20.f) ? v : log1pf(__expf(v));
            }
            C[(size_t)m * ldc + n] = v;
        }
    }
}

// ---------------- causal depthwise conv (K=4) + SiLU ----------------
__global__ void conv_silu_kernel(const float* __restrict__ xz,
                                 const float* __restrict__ w,
                                 const float* __restrict__ bias,
                                 float* __restrict__ uc) {
    int idx = blockIdx.x * blockDim.x + threadIdx.x;  // t*EDIM + e
    if (idx >= TOK * EDIM) return;
    int e = idx & (EDIM - 1);
    int t = idx >> 11;
    int b = t >> 11;
    int l = t & (SEQ - 1);
    float acc = bias[e];
    #pragma unroll
    for (int j = 0; j < KCONV; j++) {
        int ll = l - (KCONV - 1) + j;
        if (ll >= 0)
            acc = fmaf(xz[(size_t)(b * SEQ + ll) * (2 * EDIM) + e],
                       w[e * KCONV + j], acc);
    }
    uc[idx] = acc / (1.f + __expf(-acc));  // SiLU
}

// ---------------- chunked selective scan, thread-per-(b,c,e) --------------
__global__ void __launch_bounds__(256) scan_pass1(
        const float* __restrict__ dt,
        const float* __restrict__ u,
        const float* __restrict__ xdbl,
        const float* __restrict__ A_log,
        float* __restrict__ hloc,
        float* __restrict__ ssum) {
    const int e = blockIdx.x * 256 + threadIdx.x;
    const int c = blockIdx.y, b = blockIdx.z;
    __shared__ float4 sB[CLEN][NSTATE/4];
    const int t0 = b * SEQ + c * CLEN;
    for (int i = threadIdx.x; i < CLEN * NSTATE / 4; i += 256) {
        int l = i / (NSTATE/4), q = i % (NSTATE/4);
        sB[l][q] = *(const float4*)&xdbl[(size_t)(t0 + l) * XDBL + RRANK + q * 4];
    }
    __syncthreads();
    float Aen[NSTATE];
    #pragma unroll
    for (int q = 0; q < 4; q++) {
        float4 a = *(const float4*)&A_log[e * NSTATE + q * 4];
        Aen[q*4+0] = -__expf(a.x); Aen[q*4+1] = -__expf(a.y);
        Aen[q*4+2] = -__expf(a.z); Aen[q*4+3] = -__expf(a.w);
    }
    float h[NSTATE];
    #pragma unroll
    for (int n = 0; n < NSTATE; n++) h[n] = 0.f;
    float s = 0.f;
    for (int l = 0; l < CLEN; l++) {
        int t = t0 + l;
        float dtv = dt[(size_t)t * EDIM + e];
        float uv  = u [(size_t)t * EDIM + e];
        s += dtv;
        float du = dtv * uv;
        #pragma unroll
        for (int q = 0; q < 4; q++) {
            float4 Bv = sB[l][q];
            h[q*4+0] = fmaf(h[q*4+0], __expf(dtv * Aen[q*4+0]), du * Bv.x);
            h[q*4+1] = fmaf(h[q*4+1], __expf(dtv * Aen[q*4+1]), du * Bv.y);
            h[q*4+2] = fmaf(h[q*4+2], __expf(dtv * Aen[q*4+2]), du * Bv.z);
            h[q*4+3] = fmaf(h[q*4+3], __expf(dtv * Aen[q*4+3]), du * Bv.w);
        }
    }
    size_t g = ((size_t)(b * EDIM + e) * NCHUNK + c);
    #pragma unroll
    for (int q = 0; q < 4; q++)
        *(float4*)&hloc[g * NSTATE + q * 4] =
            make_float4(h[q*4+0], h[q*4+1], h[q*4+2], h[q*4+3]);
    ssum[g] = s;
}

__global__ void scan_pass2(const float* __restrict__ A_log,
                           const float* __restrict__ ssum,
                           const float* __restrict__ hloc,
                           float* __restrict__ hstart) {
    int i = blockIdx.x * 256 + threadIdx.x;
    int n = i & 15;
    int e = (i >> 4) & (EDIM - 1);
    int b = i >> 15;
    float Aen = -__expf(A_log[e * NSTATE + n]);
    float h = 0.f;
    int gbase = (b * EDIM + e) * NCHUNK;
    for (int c = 0; c < NCHUNK; c++) {
        int g = gbase + c;
        hstart[(size_t)g * NSTATE + n] = h;
        h = fmaf(h, __expf(Aen * ssum[g]), hloc[(size_t)g * NSTATE + n]);
    }
}

__global__ void __launch_bounds__(256) scan_pass3(
        const float* __restrict__ dt,
        const float* __restrict__ u,
        const float* __restrict__ xz,
        const float* __restrict__ xdbl,
        const float* __restrict__ A_log,
        const float* __restrict__ Dp,
        const float* __restrict__ hstart,
        __nv_bfloat16* __restrict__ yh,
        __nv_bfloat16* __restrict__ yl) {
    const int e = blockIdx.x * 256 + threadIdx.x;
    const int c = blockIdx.y, b = blockIdx.z;
    __shared__ float4 sB[CLEN][NSTATE/4];
    __shared__ float4 sC[CLEN][NSTATE/4];
    const int t0 = b * SEQ + c * CLEN;
    for (int i = threadIdx.x; i < CLEN * NSTATE / 4; i += 256) {
        int l = i / (NSTATE/4), q = i % (NSTATE/4);
        sB[l][q] = *(const float4*)&xdbl[(size_t)(t0 + l) * XDBL + RRANK + q * 4];
        sC[l][q] = *(const float4*)&xdbl[(size_t)(t0 + l) * XDBL + RRANK + NSTATE + q * 4];
    }
    __syncthreads();
    float Aen[NSTATE];
    #pragma unroll
    for (int q = 0; q < 4; q++) {
        float4 a = *(const float4*)&A_log[e * NSTATE + q * 4];
        Aen[q*4+0] = -__expf(a.x); Aen[q*4+1] = -__expf(a.y);
        Aen[q*4+2] = -__expf(a.z); Aen[q*4+3] = -__expf(a.w);
    }
    const float Dv = Dp[e];
    size_t g = ((size_t)(b * EDIM + e) * NCHUNK + c);
    float h[NSTATE];
    #pragma unroll
    for (int q = 0; q < 4; q++) {
        float4 v = *(const float4*)&hstart[g * NSTATE + q * 4];
        h[q*4+0] = v.x; h[q*4+1] = v.y; h[q*4+2] = v.z; h[q*4+3] = v.w;
    }
    for (int l = 0; l < CLEN; l++) {
        int t = t0 + l;
        float dtv = dt[(size_t)t * EDIM + e];
        float uv  = u [(size_t)t * EDIM + e];
        float du = dtv * uv;
        float p = 0.f;
        #pragma unroll
        for (int q = 0; q < 4; q++) {
            float4 Bv = sB[l][q];
            float4 Cv = sC[l][q];
            h[q*4+0] = fmaf(h[q*4+0], __expf(dtv * Aen[q*4+0]), du * Bv.x);
            h[q*4+1] = fmaf(h[q*4+1], __expf(dtv * Aen[q*4+1]), du * Bv.y);
            h[q*4+2] = fmaf(h[q*4+2], __expf(dtv * Aen[q*4+2]), du * Bv.z);
            h[q*4+3] = fmaf(h[q*4+3], __expf(dtv * Aen[q*4+3]), du * Bv.w);
            p = fmaf(h[q*4+0], Cv.x, p);
            p = fmaf(h[q*4+1], Cv.y, p);
            p = fmaf(h[q*4+2], Cv.z, p);
            p = fmaf(h[q*4+3], Cv.w, p);
        }
        float zv = xz[(size_t)t * (2 * EDIM) + EDIM + e];
        float sz = zv / (1.f + __expf(-zv));
        float yv = (p + uv * Dv) * sz;
        __nv_bfloat16 hb = __float2bfloat16(yv);
        yh[(size_t)t * EDIM + e] = hb;
        yl[(size_t)t * EDIM + e] = __float2bfloat16(yv - __bfloat162float(hb));
    }
}

// ---------------- launch ----------------
extern "C" void kernel_launch(void* const* d_in, const int* in_sizes, int n_in,
                              void* d_out, int out_size) {
    const float* x         = (const float*)d_in[0];
    const float* norm_w    = (const float*)d_in[1];
    const float* in_proj_w = (const float*)d_in[2];
    const float* conv_w    = (const float*)d_in[3];
    const float* conv_b    = (const float*)d_in[4];
    const float* x_proj_w  = (const float*)d_in[5];
    const float* dt_proj_w = (const float*)d_in[6];
    const float* dt_proj_b = (const float*)d_in[7];
    const float* A_log     = (const float*)d_in[8];
    const float* Dp        = (const float*)d_in[9];
    const float* out_proj_w= (const float*)d_in[10];
    float* out = (float*)d_out;

    float *p_xz, *p_uc, *p_xdbl, *p_dt, *p_hloc, *p_hstart, *p_ssum;
    cudaGetSymbolAddress((void**)&p_xz,    g_xz);
    cudaGetSymbolAddress((void**)&p_uc,    g_uc);
    cudaGetSymbolAddress((void**)&p_xdbl,  g_xdbl);
    cudaGetSymbolAddress((void**)&p_dt,    g_dt);
    cudaGetSymbolAddress((void**)&p_hloc,  g_hloc);
    cudaGetSymbolAddress((void**)&p_hstart,g_hstart);
    cudaGetSymbolAddress((void**)&p_ssum,  g_ssum);
    __nv_bfloat16 *p_xnh, *p_xnl, *p_wih, *p_wil, *p_yh, *p_yl, *p_woh, *p_wol;
    cudaGetSymbolAddress((void**)&p_xnh, g_xnh);
    cudaGetSymbolAddress((void**)&p_xnl, g_xnl);
    cudaGetSymbolAddress((void**)&p_wih, g_wih);
    cudaGetSymbolAddress((void**)&p_wil, g_wil);
    cudaGetSymbolAddress((void**)&p_yh,  g_yh);
    cudaGetSymbolAddress((void**)&p_yl,  g_yl);
    cudaGetSymbolAddress((void**)&p_woh, g_woh);
    cudaGetSymbolAddress((void**)&p_wol, g_wol);

    const int SMEM_PIPE = NSTAGE * STAGE_B;  // 98304
    cudaFuncSetAttribute(gemm_bf16x3_pipe<0>,
                         cudaFuncAttributeMaxDynamicSharedMemorySize, SMEM_PIPE);
    cudaFuncSetAttribute(gemm_bf16x3_pipe<2>,
                         cudaFuncAttributeMaxDynamicSharedMemorySize, SMEM_PIPE);

    // 1. RMSNorm fused with bf16 split
    rmsnorm_split_kernel<<<TOK, 256>>>(x, norm_w, p_xnh, p_xnl);

    // 2-3. weight splits
    split_kernel<<<(2*EDIM*DM + 255)/256, 256>>>(in_proj_w, p_wih, p_wil, 2*EDIM*DM);
    split_kernel<<<(DM*EDIM + 255)/256, 256>>>(out_proj_w, p_woh, p_wol, DM*EDIM);

    // 4. in_proj (tensor cores, 4-stage pipeline)
    gemm_bf16x3_pipe<0><<<dim3(2*EDIM/128, TOK/128), 256, SMEM_PIPE>>>(
        p_xnh, p_xnl, p_wih, p_wil, p_xz, DM, 2*EDIM, nullptr);

    // 5. conv + SiLU
    conv_silu_kernel<<<(TOK*EDIM)/256, 256>>>(p_xz, conv_w, conv_b, p_uc);

    // 6. x_proj: [4096,2048] @ [96,2048]^T -> [4096,96]
    gemm_nt_kernel<32,96,32,4,6,0><<<dim3(1, TOK/32), 128>>>(
        p_uc, x_proj_w, p_xdbl, EDIM, EDIM, EDIM, XDBL, nullptr);

    // 7. dt_proj + bias + softplus: [4096,64] @ [2048,64]^T -> [4096,2048]
    gemm_nt_kernel<128,128,16,8,8,1><<<dim3(EDIM/128, TOK/128), 256>>>(
        p_xdbl, dt_proj_w, p_dt, RRANK, XDBL, RRANK, EDIM, dt_proj_b);

    // 8-10. chunked selective scan (+ D skip + z gate + bf16 split)
    scan_pass1<<<dim3(EDIM/256, NCHUNK, BATCH), 256>>>(
        p_dt, p_uc, p_xdbl, A_log, p_hloc, p_ssum);
    scan_pass2<<<BATCH*EDIM*NSTATE/256, 256>>>(A_log, p_ssum, p_hloc, p_hstart);
    scan_pass3<<<dim3(EDIM/256, NCHUNK, BATCH), 256>>>(
        p_dt, p_uc, p_xz, p_xdbl, A_log, Dp, p_hstart, p_yh, p_yl);

    // 11. out_proj + residual
    gemm_bf16x3_pipe<2><<<dim3(DM/128, TOK/128), 256, SMEM_PIPE>>>(
        p_yh, p_yl, p_woh, p_wol, out, EDIM, DM, x);
}

// round 9
// speedup vs baseline: 4.5509x; 1.1207x over previous
#include <cuda_runtime.h>
#include <cuda_fp16.h>
#include <cuda_bf16.h>
#include <math.h>
#include <stdint.h>

// Problem constants
#define BATCH 2
#define SEQ   2048
#define TOK   (BATCH*SEQ)      // 4096 tokens
#define DM    1024
#define EDIM  2048
#define NSTATE 16
#define KCONV 4
#define RRANK 64
#define XDBL  (RRANK + 2*NSTATE)   // 96
#define EPSV  1e-5f
#define NCHUNK 32
#define CLEN   64              // NCHUNK*CLEN = SEQ

// ---------------- scratch (device globals, no allocation) ----------------
__device__ float g_xz  [TOK * 2 * EDIM];  // in_proj output (u | z)
__device__ float g_uc  [TOK * EDIM];      // conv+silu output
__device__ float g_xdbl[TOK * XDBL];      // x_proj output (dt_low|B|C)
__device__ float g_dt  [TOK * EDIM];      // softplus(dt)
__device__ float g_hloc  [BATCH*EDIM*NCHUNK*NSTATE];
__device__ float g_hstart[BATCH*EDIM*NCHUNK*NSTATE];
__device__ float g_ssum  [BATCH*EDIM*NCHUNK];

// fp16 hi/lo splits (A side) + fp16 weights (B side, hi only)
__device__ __half g_xnh[TOK * DM],  g_xnl[TOK * DM];
__device__ __half g_wih[2*EDIM*DM];
__device__ __half g_yh [TOK * EDIM], g_yl [TOK * EDIM];
__device__ __half g_woh[DM * EDIM];

// ---------------- helpers ----------------
__device__ __forceinline__ uint32_t smem_u32(const void* p) {
    uint32_t a;
    asm("{ .reg .u64 t; cvta.to.shared.u64 t, %1; cvt.u32.u64 %0, t; }" : "=r"(a) : "l"(p));
    return a;
}
__device__ __forceinline__ void ldmx4u(uint32_t* r, uint32_t a) {
    asm volatile("ldmatrix.sync.aligned.m8n8.x4.shared.b16 {%0,%1,%2,%3}, [%4];\n"
                 : "=r"(r[0]), "=r"(r[1]), "=r"(r[2]), "=r"(r[3]) : "r"(a));
}
__device__ __forceinline__ void mma_f16(float* d, const uint32_t* a, const uint32_t* b) {
    asm volatile("mma.sync.aligned.m16n8k16.row.col.f32.f16.f16.f32 "
                 "{%0,%1,%2,%3}, {%4,%5,%6,%7}, {%8,%9}, {%0,%1,%2,%3};\n"
                 : "+f"(d[0]), "+f"(d[1]), "+f"(d[2]), "+f"(d[3])
                 : "r"(a[0]), "r"(a[1]), "r"(a[2]), "r"(a[3]), "r"(b[0]), "r"(b[1]));
}
__device__ __forceinline__ void cpa16u(uint32_t dst, const void* src) {
    asm volatile("cp.async.cg.shared.global [%0], [%1], 16;\n" :: "r"(dst), "l"(src));
}

// ---------------- fp32 -> fp16 hi/lo split ----------------
__global__ void split_h2_kernel(const float* __restrict__ src,
                                __half* __restrict__ hi,
                                __half* __restrict__ lo, int n) {
    int i = blockIdx.x * blockDim.x + threadIdx.x;
    if (i >= n) return;
    float v = src[i];
    __half h = __float2half(v);
    hi[i] = h;
    lo[i] = __float2half(v - __half2float(h));
}
// fp32 -> fp16 convert (weights, hi only)
__global__ void cvt_h_kernel(const float* __restrict__ src,
                             __half* __restrict__ dst, int n) {
    int i = blockIdx.x * blockDim.x + threadIdx.x;
    if (i >= n) return;
    dst[i] = __float2half(src[i]);
}

// ---------------- RMSNorm fused with fp16 hi/lo split ----------------
__global__ void rmsnorm_split_kernel(const float* __restrict__ x,
                                     const float* __restrict__ nw,
                                     __half* __restrict__ xnh,
                                     __half* __restrict__ xnl) {
    int t = blockIdx.x;
    const float* row = x + (size_t)t * DM;
    float ss = 0.f;
    for (int i = threadIdx.x; i < DM; i += 256) {
        float v = row[i];
        ss += v * v;
    }
    for (int o = 16; o > 0; o >>= 1) ss += __shfl_xor_sync(0xffffffffu, ss, o);
    __shared__ float sred[8];
    int wid = threadIdx.x >> 5, lid = threadIdx.x & 31;
    if (lid == 0) sred[wid] = ss;
    __syncthreads();
    __shared__ float s_scale;
    if (threadIdx.x == 0) {
        float tot = 0.f;
        #pragma unroll
        for (int i = 0; i < 8; i++) tot += sred[i];
        s_scale = rsqrtf(tot / (float)DM + EPSV);
    }
    __syncthreads();
    float sc = s_scale;
    for (int i = threadIdx.x; i < DM; i += 256) {
        float v = row[i] * sc * nw[i];
        __half h = __float2half(v);
        xnh[(size_t)t * DM + i] = h;
        xnl[(size_t)t * DM + i] = __float2half(v - __half2float(h));
    }
}

// ---------------- fp16 2-term tensor-core GEMM, 4-stage BK=16 ------------
// C[M,N] = A[M,K]*B[N,K]^T with A ~ Ah+Al (fp16 pair), B ~ Bh (fp16).
// C ≈ Ah*Bh + Al*Bh.
// block 128x128, 8 warps (2x4), warp tile 64x32, lookahead 2 chunks,
// single __syncthreads per chunk. Row stride 48B: conflict-free ldmatrix.
// EPI: 0 = plain, 2 = +resid
#define ROWB 48
#define BUF_B (128*ROWB)       // 6144 per matrix per stage
#define STAGE_B (3*BUF_B)      // 18432
#define NSTAGE 4
template<int EPI>
__global__ void __launch_bounds__(256, 2)
gemm_f16x2_pipe(const __half* __restrict__ Ah, const __half* __restrict__ Al,
                const __half* __restrict__ Bh,
                float* __restrict__ C, int Kd, int ldc,
                const float* __restrict__ resid) {
    extern __shared__ char dsm[];
    const uint32_t dbase = smem_u32(dsm);
    const int tid = threadIdx.x;
    const int lane = tid & 31, warp = tid >> 5;
    const int wm = warp >> 2, wn = warp & 3;
    const int m0 = blockIdx.y * 128, n0 = blockIdx.x * 128;

    const __half* src[3] = {Ah + (size_t)m0 * Kd, Al + (size_t)m0 * Kd,
                            Bh + (size_t)n0 * Kd};

    float acc[4][4][4];
    #pragma unroll
    for (int i = 0; i < 4; i++)
        #pragma unroll
        for (int j = 0; j < 4; j++)
            #pragma unroll
            for (int r = 0; r < 4; r++) acc[i][j][r] = 0.f;

    // per-thread load map: 768 16B chunks/stage, 3 per thread
    auto issue = [&](int k0, int st) {
        uint32_t sb = dbase + st * STAGE_B;
        #pragma unroll
        for (int it = 0; it < 3; it++) {
            int idx = tid + it * 256;
            int buf = idx >> 8;
            int i = idx & 255;
            int r = i >> 1, j = i & 1;
            cpa16u(sb + buf * BUF_B + r * ROWB + j * 16,
                   src[buf] + (size_t)r * Kd + k0 + j * 8);
        }
        asm volatile("cp.async.commit_group;\n");
    };

    const int KT = Kd >> 4;   // chunks of 16
    issue(0, 0);
    issue(16, 1);

    const uint32_t a_off = (uint32_t)((wm * 64 + (lane & 15)) * ROWB + (lane >> 4) * 16);
    const uint32_t b_off = (uint32_t)((wn * 32 + (lane & 7) + 8 * (lane >> 4)) * ROWB
                                      + ((lane >> 3) & 1) * 16);

    for (int kt = 0; kt < KT; kt++) {
        if (kt + 2 < KT) {
            issue((kt + 2) << 4, (kt + 2) & 3);
            asm volatile("cp.async.wait_group 2;\n");
        } else if (kt + 1 < KT) {
            asm volatile("cp.async.wait_group 1;\n");
        } else {
            asm volatile("cp.async.wait_group 0;\n");
        }
        __syncthreads();

        uint32_t sb = dbase + (kt & 3) * STAGE_B;
        uint32_t ah[4][4], al[4][4], bh[4][2];
        #pragma unroll
        for (int mt = 0; mt < 4; mt++) {
            ldmx4u(ah[mt], sb + a_off + mt * 16 * ROWB);
            ldmx4u(al[mt], sb + BUF_B + a_off + mt * 16 * ROWB);
        }
        #pragma unroll
        for (int np = 0; np < 2; np++) {
            uint32_t t[4];
            ldmx4u(t, sb + 2 * BUF_B + b_off + np * 16 * ROWB);
            bh[2*np][0] = t[0]; bh[2*np][1] = t[1];
            bh[2*np+1][0] = t[2]; bh[2*np+1][1] = t[3];
        }
        #pragma unroll
        for (int mt = 0; mt < 4; mt++)
            #pragma unroll
            for (int nt = 0; nt < 4; nt++) {
                mma_f16(acc[mt][nt], ah[mt], bh[nt]);
                mma_f16(acc[mt][nt], al[mt], bh[nt]);
            }
    }

    const int gr = lane >> 2, gc2 = (lane & 3) * 2;
    #pragma unroll
    for (int mt = 0; mt < 4; mt++) {
        int m = m0 + wm * 64 + mt * 16 + gr;
        #pragma unroll
        for (int nt = 0; nt < 4; nt++) {
            int n = n0 + wn * 32 + nt * 8 + gc2;
            float2 v01 = make_float2(acc[mt][nt][0], acc[mt][nt][1]);
            float2 v23 = make_float2(acc[mt][nt][2], acc[mt][nt][3]);
            if (EPI == 2) {
                const float2 r01 = *(const float2*)&resid[(size_t)m * ldc + n];
                const float2 r23 = *(const float2*)&resid[(size_t)(m + 8) * ldc + n];
                v01.x += r01.x; v01.y += r01.y;
                v23.x += r23.x; v23.y += r23.y;
            }
            *(float2*)&C[(size_t)m * ldc + n] = v01;
            *(float2*)&C[(size_t)(m + 8) * ldc + n] = v23;
        }
    }
}

// ---------------- Tiled SGEMM (small GEMMs): C = A * B^T (+ epilogue) -----
// EPI: 0 = plain, 1 = softplus(acc + bias[n])
template<int BM, int BN, int BK, int TM, int TN, int EPI>
__global__ void gemm_nt_kernel(const float* __restrict__ A,
                               const float* __restrict__ Bw,
                               float* __restrict__ C,
                               int Kd, int lda, int ldb, int ldc,
                               const float* __restrict__ bias) {
    constexpr int THREADS = (BM / TM) * (BN / TN);
    __shared__ float As[BK][BM + 4];
    __shared__ float Bs[BK][BN + 4];
    const int tid = threadIdx.x;
    const int tx = tid % (BN / TN);
    const int ty = tid / (BN / TN);
    const int m0 = blockIdx.y * BM;
    const int n0 = blockIdx.x * BN;

    float acc[TM][TN];
    #pragma unroll
    for (int i = 0; i < TM; i++)
        #pragma unroll
        for (int j = 0; j < TN; j++) acc[i][j] = 0.f;

    for (int k0 = 0; k0 < Kd; k0 += BK) {
        const int A_F4 = BM * BK / 4;
        for (int i = tid; i < A_F4; i += THREADS) {
            int r  = i / (BK / 4);
            int c4 = i % (BK / 4);
            float4 v = *(const float4*)&A[(size_t)(m0 + r) * lda + k0 + c4 * 4];
            As[c4 * 4 + 0][r] = v.x;
            As[c4 * 4 + 1][r] = v.y;
            As[c4 * 4 + 2][r] = v.z;
            As[c4 * 4 + 3][r] = v.w;
        }
        const int B_F4 = BN * BK / 4;
        for (int i = tid; i < B_F4; i += THREADS) {
            int r  = i / (BK / 4);
            int c4 = i % (BK / 4);
            float4 v = *(const float4*)&Bw[(size_t)(n0 + r) * ldb + k0 + c4 * 4];
            Bs[c4 * 4 + 0][r] = v.x;
            Bs[c4 * 4 + 1][r] = v.y;
            Bs[c4 * 4 + 2][r] = v.z;
            Bs[c4 * 4 + 3][r] = v.w;
        }
        __syncthreads();
        #pragma unroll
        for (int kk = 0; kk < BK; kk++) {
            float ra[TM], rb[TN];
            #pragma unroll
            for (int i = 0; i < TM; i++) ra[i] = As[kk][ty * TM + i];
            #pragma unroll
            for (int j = 0; j < TN; j++) rb[j] = Bs[kk][tx * TN + j];
            #pragma unroll
            for (int i = 0; i < TM; i++)
                #pragma unroll
                for (int j = 0; j < TN; j++)
                    acc[i][j] = fmaf(ra[i], rb[j], acc[i][j]);
        }
        __syncthreads();
    }

    #pragma unroll
    for (int i = 0; i < TM; i++) {
        int m = m0 + ty * TM + i;
        #pragma unroll
        for (int j = 0; j < TN; j++) {
            int n = n0 + tx * TN + j;
            float v = acc[i][j];
            if (EPI == 1) {
                v += bias[n];
                v = (v > 20.f) ? v : log1pf(__expf(v));
            }
            C[(size_t)m * ldc + n] = v;
        }
    }
}

// ---------------- causal depthwise conv (K=4) + SiLU ----------------
__global__ void conv_silu_kernel(const float* __restrict__ xz,
                                 const float* __restrict__ w,
                                 const float* __restrict__ bias,
                                 float* __restrict__ uc) {
    int idx = blockIdx.x * blockDim.x + threadIdx.x;  // t*EDIM + e
    if (idx >= TOK * EDIM) return;
    int e = idx & (EDIM - 1);
    int t = idx >> 11;
    int b = t >> 11;
    int l = t & (SEQ - 1);
    float acc = bias[e];
    #pragma unroll
    for (int j = 0; j < KCONV; j++) {
        int ll = l - (KCONV - 1) + j;
        if (ll >= 0)
            acc = fmaf(xz[(size_t)(b * SEQ + ll) * (2 * EDIM) + e],
                       w[e * KCONV + j], acc);
    }
    uc[idx] = acc / (1.f + __expf(-acc));  // SiLU
}

// ---------------- chunked selective scan, thread-per-(b,c,e) --------------
__global__ void __launch_bounds__(256) scan_pass1(
        const float* __restrict__ dt,
        const float* __restrict__ u,
        const float* __restrict__ xdbl,
        const float* __restrict__ A_log,
        float* __restrict__ hloc,
        float* __restrict__ ssum) {
    const int e = blockIdx.x * 256 + threadIdx.x;
    const int c = blockIdx.y, b = blockIdx.z;
    __shared__ float4 sB[CLEN][NSTATE/4];
    const int t0 = b * SEQ + c * CLEN;
    for (int i = threadIdx.x; i < CLEN * NSTATE / 4; i += 256) {
        int l = i / (NSTATE/4), q = i % (NSTATE/4);
        sB[l][q] = *(const float4*)&xdbl[(size_t)(t0 + l) * XDBL + RRANK + q * 4];
    }
    __syncthreads();
    float Aen[NSTATE];
    #pragma unroll
    for (int q = 0; q < 4; q++) {
        float4 a = *(const float4*)&A_log[e * NSTATE + q * 4];
        Aen[q*4+0] = -__expf(a.x); Aen[q*4+1] = -__expf(a.y);
        Aen[q*4+2] = -__expf(a.z); Aen[q*4+3] = -__expf(a.w);
    }
    float h[NSTATE];
    #pragma unroll
    for (int n = 0; n < NSTATE; n++) h[n] = 0.f;
    float s = 0.f;
    for (int l = 0; l < CLEN; l++) {
        int t = t0 + l;
        float dtv = dt[(size_t)t * EDIM + e];
        float uv  = u [(size_t)t * EDIM + e];
        s += dtv;
        float du = dtv * uv;
        #pragma unroll
        for (int q = 0; q < 4; q++) {
            float4 Bv = sB[l][q];
            h[q*4+0] = fmaf(h[q*4+0], __expf(dtv * Aen[q*4+0]), du * Bv.x);
            h[q*4+1] = fmaf(h[q*4+1], __expf(dtv * Aen[q*4+1]), du * Bv.y);
            h[q*4+2] = fmaf(h[q*4+2], __expf(dtv * Aen[q*4+2]), du * Bv.z);
            h[q*4+3] = fmaf(h[q*4+3], __expf(dtv * Aen[q*4+3]), du * Bv.w);
        }
    }
    size_t g = ((size_t)(b * EDIM + e) * NCHUNK + c);
    #pragma unroll
    for (int q = 0; q < 4; q++)
        *(float4*)&hloc[g * NSTATE + q * 4] =
            make_float4(h[q*4+0], h[q*4+1], h[q*4+2], h[q*4+3]);
    ssum[g] = s;
}

__global__ void scan_pass2(const float* __restrict__ A_log,
                           const float* __restrict__ ssum,
                           const float* __restrict__ hloc,
                           float* __restrict__ hstart) {
    int i = blockIdx.x * 256 + threadIdx.x;
    int n = i & 15;
    int e = (i >> 4) & (EDIM - 1);
    int b = i >> 15;
    float Aen = -__expf(A_log[e * NSTATE + n]);
    float h = 0.f;
    int gbase = (b * EDIM + e) * NCHUNK;
    for (int c = 0; c < NCHUNK; c++) {
        int g = gbase + c;
        hstart[(size_t)g * NSTATE + n] = h;
        h = fmaf(h, __expf(Aen * ssum[g]), hloc[(size_t)g * NSTATE + n]);
    }
}

__global__ void __launch_bounds__(256) scan_pass3(
        const float* __restrict__ dt,
        const float* __restrict__ u,
        const float* __restrict__ xz,
        const float* __restrict__ xdbl,
        const float* __restrict__ A_log,
        const float* __restrict__ Dp,
        const float* __restrict__ hstart,
        __half* __restrict__ yh,
        __half* __restrict__ yl) {
    const int e = blockIdx.x * 256 + threadIdx.x;
    const int c = blockIdx.y, b = blockIdx.z;
    __shared__ float4 sB[CLEN][NSTATE/4];
    __shared__ float4 sC[CLEN][NSTATE/4];
    const int t0 = b * SEQ + c * CLEN;
    for (int i = threadIdx.x; i < CLEN * NSTATE / 4; i += 256) {
        int l = i / (NSTATE/4), q = i % (NSTATE/4);
        sB[l][q] = *(const float4*)&xdbl[(size_t)(t0 + l) * XDBL + RRANK + q * 4];
        sC[l][q] = *(const float4*)&xdbl[(size_t)(t0 + l) * XDBL + RRANK + NSTATE + q * 4];
    }
    __syncthreads();
    float Aen[NSTATE];
    #pragma unroll
    for (int q = 0; q < 4; q++) {
        float4 a = *(const float4*)&A_log[e * NSTATE + q * 4];
        Aen[q*4+0] = -__expf(a.x); Aen[q*4+1] = -__expf(a.y);
        Aen[q*4+2] = -__expf(a.z); Aen[q*4+3] = -__expf(a.w);
    }
    const float Dv = Dp[e];
    size_t g = ((size_t)(b * EDIM + e) * NCHUNK + c);
    float h[NSTATE];
    #pragma unroll
    for (int q = 0; q < 4; q++) {
        float4 v = *(const float4*)&hstart[g * NSTATE + q * 4];
        h[q*4+0] = v.x; h[q*4+1] = v.y; h[q*4+2] = v.z; h[q*4+3] = v.w;
    }
    for (int l = 0; l < CLEN; l++) {
        int t = t0 + l;
        float dtv = dt[(size_t)t * EDIM + e];
        float uv  = u [(size_t)t * EDIM + e];
        float du = dtv * uv;
        float p = 0.f;
        #pragma unroll
        for (int q = 0; q < 4; q++) {
            float4 Bv = sB[l][q];
            float4 Cv = sC[l][q];
            h[q*4+0] = fmaf(h[q*4+0], __expf(dtv * Aen[q*4+0]), du * Bv.x);
            h[q*4+1] = fmaf(h[q*4+1], __expf(dtv * Aen[q*4+1]), du * Bv.y);
            h[q*4+2] = fmaf(h[q*4+2], __expf(dtv * Aen[q*4+2]), du * Bv.z);
            h[q*4+3] = fmaf(h[q*4+3], __expf(dtv * Aen[q*4+3]), du * Bv.w);
            p = fmaf(h[q*4+0], Cv.x, p);
            p = fmaf(h[q*4+1], Cv.y, p);
            p = fmaf(h[q*4+2], Cv.z, p);
            p = fmaf(h[q*4+3], Cv.w, p);
        }
        float zv = xz[(size_t)t * (2 * EDIM) + EDIM + e];
        float sz = zv / (1.f + __expf(-zv));
        float yv = (p + uv * Dv) * sz;
        __half hb = __float2half(yv);
        yh[(size_t)t * EDIM + e] = hb;
        yl[(size_t)t * EDIM + e] = __float2half(yv - __half2float(hb));
    }
}

// ---------------- launch ----------------
extern "C" void kernel_launch(void* const* d_in, const int* in_sizes, int n_in,
                              void* d_out, int out_size) {
    const float* x         = (const float*)d_in[0];
    const float* norm_w    = (const float*)d_in[1];
    const float* in_proj_w = (const float*)d_in[2];
    const float* conv_w    = (const float*)d_in[3];
    const float* conv_b    = (const float*)d_in[4];
    const float* x_proj_w  = (const float*)d_in[5];
    const float* dt_proj_w = (const float*)d_in[6];
    const float* dt_proj_b = (const float*)d_in[7];
    const float* A_log     = (const float*)d_in[8];
    const float* Dp        = (const float*)d_in[9];
    const float* out_proj_w= (const float*)d_in[10];
    float* out = (float*)d_out;

    float *p_xz, *p_uc, *p_xdbl, *p_dt, *p_hloc, *p_hstart, *p_ssum;
    cudaGetSymbolAddress((void**)&p_xz,    g_xz);
    cudaGetSymbolAddress((void**)&p_uc,    g_uc);
    cudaGetSymbolAddress((void**)&p_xdbl,  g_xdbl);
    cudaGetSymbolAddress((void**)&p_dt,    g_dt);
    cudaGetSymbolAddress((void**)&p_hloc,  g_hloc);
    cudaGetSymbolAddress((void**)&p_hstart,g_hstart);
    cudaGetSymbolAddress((void**)&p_ssum,  g_ssum);
    __half *p_xnh, *p_xnl, *p_wih, *p_yh, *p_yl, *p_woh;
    cudaGetSymbolAddress((void**)&p_xnh, g_xnh);
    cudaGetSymbolAddress((void**)&p_xnl, g_xnl);
    cudaGetSymbolAddress((void**)&p_wih, g_wih);
    cudaGetSymbolAddress((void**)&p_yh,  g_yh);
    cudaGetSymbolAddress((void**)&p_yl,  g_yl);
    cudaGetSymbolAddress((void**)&p_woh, g_woh);

    const int SMEM_PIPE = NSTAGE * STAGE_B;  // 73728
    cudaFuncSetAttribute(gemm_f16x2_pipe<0>,
                         cudaFuncAttributeMaxDynamicSharedMemorySize, SMEM_PIPE);
    cudaFuncSetAttribute(gemm_f16x2_pipe<2>,
                         cudaFuncAttributeMaxDynamicSharedMemorySize, SMEM_PIPE);

    // 1. RMSNorm fused with fp16 split
    rmsnorm_split_kernel<<<TOK, 256>>>(x, norm_w, p_xnh, p_xnl);

    // 2-3. weight converts (fp16 hi only)
    cvt_h_kernel<<<(2*EDIM*DM + 255)/256, 256>>>(in_proj_w, p_wih, 2*EDIM*DM);
    cvt_h_kernel<<<(DM*EDIM + 255)/256, 256>>>(out_proj_w, p_woh, DM*EDIM);

    // 4. in_proj (tensor cores, fp16 2-term)
    gemm_f16x2_pipe<0><<<dim3(2*EDIM/128, TOK/128), 256, SMEM_PIPE>>>(
        p_xnh, p_xnl, p_wih, p_xz, DM, 2*EDIM, nullptr);

    // 5. conv + SiLU
    conv_silu_kernel<<<(TOK*EDIM)/256, 256>>>(p_xz, conv_w, conv_b, p_uc);

    // 6. x_proj: [4096,2048] @ [96,2048]^T -> [4096,96]
    gemm_nt_kernel<32,96,32,4,6,0><<<dim3(1, TOK/32), 128>>>(
        p_uc, x_proj_w, p_xdbl, EDIM, EDIM, EDIM, XDBL, nullptr);

    // 7. dt_proj + bias + softplus: [4096,64] @ [2048,64]^T -> [4096,2048]
    gemm_nt_kernel<128,128,16,8,8,1><<<dim3(EDIM/128, TOK/128), 256>>>(
        p_xdbl, dt_proj_w, p_dt, RRANK, XDBL, RRANK, EDIM, dt_proj_b);

    // 8-10. chunked selective scan (+ D skip + z gate + fp16 split)
    scan_pass1<<<dim3(EDIM/256, NCHUNK, BATCH), 256>>>(
        p_dt, p_uc, p_xdbl, A_log, p_hloc, p_ssum);
    scan_pass2<<<BATCH*EDIM*NSTATE/256, 256>>>(A_log, p_ssum, p_hloc, p_hstart);
    scan_pass3<<<dim3(EDIM/256, NCHUNK, BATCH), 256>>>(
        p_dt, p_uc, p_xz, p_xdbl, A_log, Dp, p_hstart, p_yh, p_yl);

    // 11. out_proj + residual (fp16 2-term)
    gemm_f16x2_pipe<2><<<dim3(DM/128, TOK/128), 256, SMEM_PIPE>>>(
        p_yh, p_yl, p_woh, out, EDIM, DM, x);
}

// round 10
// speedup vs baseline: 6.3134x; 1.3873x over previous
#include <cuda_runtime.h>
#include <cuda_fp16.h>
#include <math.h>
#include <stdint.h>

// Problem constants
#define BATCH 2
#define SEQ   2048
#define TOK   (BATCH*SEQ)      // 4096 tokens
#define DM    1024
#define EDIM  2048
#define NSTATE 16
#define KCONV 4
#define RRANK 64
#define XDBL  (RRANK + 2*NSTATE)   // 96
#define EPSV  1e-5f
#define NCHUNK 32
#define CLEN   64              // NCHUNK*CLEN = SEQ

// ---------------- scratch (device globals, no allocation) ----------------
__device__ float g_xz  [TOK * 2 * EDIM];  // in_proj output (u | z)
__device__ float g_uc  [TOK * EDIM];      // conv+silu output (fp32, for scan)
__device__ float g_xdbl[TOK * XDBL];      // x_proj output (dt_low|B|C)
__device__ float g_dt  [TOK * EDIM];      // softplus(dt)
__device__ float g_hloc  [BATCH*EDIM*NCHUNK*NSTATE];
__device__ float g_hstart[BATCH*EDIM*NCHUNK*NSTATE];
__device__ float g_ssum  [BATCH*EDIM*NCHUNK];

// fp16 operands
__device__ __half g_xnh[TOK * DM],  g_xnl[TOK * DM];   // rmsnorm out hi/lo
__device__ __half g_wih[2*EDIM*DM];                    // in_proj_w fp16
__device__ __half g_uh [TOK * EDIM], g_ul [TOK * EDIM];// conv out hi/lo
__device__ __half g_xpw[XDBL * EDIM];                  // x_proj_w fp16
__device__ __half g_dtlh[TOK * RRANK], g_dtll[TOK * RRANK]; // dt_low hi/lo
__device__ __half g_dtw[EDIM * RRANK];                 // dt_proj_w fp16
__device__ __half g_yh [TOK * EDIM], g_yl [TOK * EDIM];// scan out hi/lo
__device__ __half g_woh[DM * EDIM];                    // out_proj_w fp16

// ---------------- helpers ----------------
__device__ __forceinline__ uint32_t smem_u32(const void* p) {
    uint32_t a;
    asm("{ .reg .u64 t; cvta.to.shared.u64 t, %1; cvt.u32.u64 %0, t; }" : "=r"(a) : "l"(p));
    return a;
}
__device__ __forceinline__ void ldmx4u(uint32_t* r, uint32_t a) {
    asm volatile("ldmatrix.sync.aligned.m8n8.x4.shared.b16 {%0,%1,%2,%3}, [%4];\n"
                 : "=r"(r[0]), "=r"(r[1]), "=r"(r[2]), "=r"(r[3]) : "r"(a));
}
__device__ __forceinline__ void mma_f16(float* d, const uint32_t* a, const uint32_t* b) {
    asm volatile("mma.sync.aligned.m16n8k16.row.col.f32.f16.f16.f32 "
                 "{%0,%1,%2,%3}, {%4,%5,%6,%7}, {%8,%9}, {%0,%1,%2,%3};\n"
                 : "+f"(d[0]), "+f"(d[1]), "+f"(d[2]), "+f"(d[3])
                 : "r"(a[0]), "r"(a[1]), "r"(a[2]), "r"(a[3]), "r"(b[0]), "r"(b[1]));
}
__device__ __forceinline__ void cpa16u(uint32_t dst, const void* src) {
    asm volatile("cp.async.cg.shared.global [%0], [%1], 16;\n" :: "r"(dst), "l"(src));
}

// fp32 -> fp16 convert (weights)
__global__ void cvt_h_kernel(const float* __restrict__ src,
                             __half* __restrict__ dst, int n) {
    int i = blockIdx.x * blockDim.x + threadIdx.x;
    if (i >= n) return;
    dst[i] = __float2half(src[i]);
}

// ---------------- RMSNorm fused with fp16 hi/lo split ----------------
__global__ void rmsnorm_split_kernel(const float* __restrict__ x,
                                     const float* __restrict__ nw,
                                     __half* __restrict__ xnh,
                                     __half* __restrict__ xnl) {
    int t = blockIdx.x;
    const float* row = x + (size_t)t * DM;
    float ss = 0.f;
    for (int i = threadIdx.x; i < DM; i += 256) {
        float v = row[i];
        ss += v * v;
    }
    for (int o = 16; o > 0; o >>= 1) ss += __shfl_xor_sync(0xffffffffu, ss, o);
    __shared__ float sred[8];
    int wid = threadIdx.x >> 5, lid = threadIdx.x & 31;
    if (lid == 0) sred[wid] = ss;
    __syncthreads();
    __shared__ float s_scale;
    if (threadIdx.x == 0) {
        float tot = 0.f;
        #pragma unroll
        for (int i = 0; i < 8; i++) tot += sred[i];
        s_scale = rsqrtf(tot / (float)DM + EPSV);
    }
    __syncthreads();
    float sc = s_scale;
    for (int i = threadIdx.x; i < DM; i += 256) {
        float v = row[i] * sc * nw[i];
        __half h = __float2half(v);
        xnh[(size_t)t * DM + i] = h;
        xnl[(size_t)t * DM + i] = __float2half(v - __half2float(h));
    }
}

// ---------------- generalized fp16 2-term tensor-core GEMM ---------------
// C[M,N] = A[M,K]*B[N,K]^T, A ~ Ah+Al fp16, B ~ Bh fp16.
// Block 128 x (WN*32), 2*WN warps, warp tile 64x32, 4-stage BK=16 pipeline.
// EPI: 0 plain | 1 softplus(acc+bias[n]) | 2 +resid | 3 plain + fp16 aux for n<64
#define ROWB 48
#define ABUF (128*ROWB)
#define NSTAGE 4
template<int WN, int EPI>
__global__ void __launch_bounds__(WN*64, 2)
gemm_f16x2(const __half* __restrict__ Ah, const __half* __restrict__ Al,
           const __half* __restrict__ Bh,
           float* __restrict__ C, int Kd, int ldc,
           const float* __restrict__ bias, const float* __restrict__ resid,
           __half* __restrict__ auxh, __half* __restrict__ auxl) {
    constexpr int BN = WN * 32;
    constexpr int BBUF = BN * ROWB;
    constexpr int STAGE = 2 * ABUF + BBUF;
    constexpr int THREADS = WN * 64;
    constexpr int ACH = 512;          // A 16B-chunks per stage (2 bufs)
    constexpr int TOT = ACH + BN * 2; // + B chunks

    extern __shared__ char dsm[];
    const uint32_t dbase = smem_u32(dsm);
    const int tid = threadIdx.x;
    const int lane = tid & 31, warp = tid >> 5;
    const int wm = warp / WN, wn = warp % WN;
    const int m0 = blockIdx.y * 128, n0 = blockIdx.x * BN;

    const __half* srcA[2] = {Ah + (size_t)m0 * Kd, Al + (size_t)m0 * Kd};
    const __half* srcB = Bh + (size_t)n0 * Kd;

    float acc[4][4][4];
    #pragma unroll
    for (int i = 0; i < 4; i++)
        #pragma unroll
        for (int j = 0; j < 4; j++)
            #pragma unroll
            for (int r = 0; r < 4; r++) acc[i][j][r] = 0.f;

    auto issue = [&](int k0, int st) {
        uint32_t sb = dbase + st * STAGE;
        #pragma unroll
        for (int idx = tid; idx < TOT; idx += THREADS) {
            if (idx < ACH) {
                int buf = idx >> 8;
                int i = idx & 255;
                cpa16u(sb + buf * ABUF + (i >> 1) * ROWB + (i & 1) * 16,
                       srcA[buf] + (size_t)(i >> 1) * Kd + k0 + (i & 1) * 8);
            } else {
                int i = idx - ACH;
                cpa16u(sb + 2 * ABUF + (i >> 1) * ROWB + (i & 1) * 16,
                       srcB + (size_t)(i >> 1) * Kd + k0 + (i & 1) * 8);
            }
        }
        asm volatile("cp.async.commit_group;\n");
    };

    const int KT = Kd >> 4;
    issue(0, 0);
    issue(16, 1);

    const uint32_t a_off = (uint32_t)((wm * 64 + (lane & 15)) * ROWB + (lane >> 4) * 16);
    const uint32_t b_off = (uint32_t)((wn * 32 + (lane & 7) + 8 * (lane >> 4)) * ROWB
                                      + ((lane >> 3) & 1) * 16);

    for (int kt = 0; kt < KT; kt++) {
        if (kt + 2 < KT) {
            issue((kt + 2) << 4, (kt + 2) & 3);
            asm volatile("cp.async.wait_group 2;\n");
        } else if (kt + 1 < KT) {
            asm volatile("cp.async.wait_group 1;\n");
        } else {
            asm volatile("cp.async.wait_group 0;\n");
        }
        __syncthreads();

        uint32_t sb = dbase + (kt & 3) * STAGE;
        uint32_t ah[4][4], al[4][4], bh[4][2];
        #pragma unroll
        for (int mt = 0; mt < 4; mt++) {
            ldmx4u(ah[mt], sb + a_off + mt * 16 * ROWB);
            ldmx4u(al[mt], sb + ABUF + a_off + mt * 16 * ROWB);
        }
        #pragma unroll
        for (int np = 0; np < 2; np++) {
            uint32_t t[4];
            ldmx4u(t, sb + 2 * ABUF + b_off + np * 16 * ROWB);
            bh[2*np][0] = t[0]; bh[2*np][1] = t[1];
            bh[2*np+1][0] = t[2]; bh[2*np+1][1] = t[3];
        }
        #pragma unroll
        for (int mt = 0; mt < 4; mt++)
            #pragma unroll
            for (int nt = 0; nt < 4; nt++) {
                mma_f16(acc[mt][nt], ah[mt], bh[nt]);
                mma_f16(acc[mt][nt], al[mt], bh[nt]);
            }
    }

    const int gr = lane >> 2, gc2 = (lane & 3) * 2;
    #pragma unroll
    for (int mt = 0; mt < 4; mt++) {
        int m = m0 + wm * 64 + mt * 16 + gr;
        #pragma unroll
        for (int nt = 0; nt < 4; nt++) {
            int n = n0 + wn * 32 + nt * 8 + gc2;
            #pragma unroll
            for (int half = 0; half < 2; half++) {
                int mm = m + half * 8;
                float v0 = acc[mt][nt][half*2+0];
                float v1 = acc[mt][nt][half*2+1];
                if (EPI == 1) {
                    v0 += bias[n];   v0 = (v0 > 20.f) ? v0 : log1pf(__expf(v0));
                    v1 += bias[n+1]; v1 = (v1 > 20.f) ? v1 : log1pf(__expf(v1));
                } else if (EPI == 2) {
                    const float2 rv = *(const float2*)&resid[(size_t)mm * ldc + n];
                    v0 += rv.x; v1 += rv.y;
                }
                *(float2*)&C[(size_t)mm * ldc + n] = make_float2(v0, v1);
                if (EPI == 3 && n < RRANK) {
                    __half h0 = __float2half(v0), h1 = __float2half(v1);
                    auxh[(size_t)mm * RRANK + n]     = h0;
                    auxh[(size_t)mm * RRANK + n + 1] = h1;
                    auxl[(size_t)mm * RRANK + n]     = __float2half(v0 - __half2float(h0));
                    auxl[(size_t)mm * RRANK + n + 1] = __float2half(v1 - __half2float(h1));
                }
            }
        }
    }
}

// ---------------- causal depthwise conv (K=4) + SiLU + fp16 split --------
__global__ void conv_silu_kernel(const float* __restrict__ xz,
                                 const float* __restrict__ w,
                                 const float* __restrict__ bias,
                                 float* __restrict__ uc,
                                 __half* __restrict__ uh,
                                 __half* __restrict__ ul) {
    int idx = blockIdx.x * blockDim.x + threadIdx.x;  // t*EDIM + e
    if (idx >= TOK * EDIM) return;
    int e = idx & (EDIM - 1);
    int t = idx >> 11;
    int b = t >> 11;
    int l = t & (SEQ - 1);
    float acc = bias[e];
    #pragma unroll
    for (int j = 0; j < KCONV; j++) {
        int ll = l - (KCONV - 1) + j;
        if (ll >= 0)
            acc = fmaf(xz[(size_t)(b * SEQ + ll) * (2 * EDIM) + e],
                       w[e * KCONV + j], acc);
    }
    float v = acc / (1.f + __expf(-acc));  // SiLU
    uc[idx] = v;
    __half h = __float2half(v);
    uh[idx] = h;
    ul[idx] = __float2half(v - __half2float(h));
}

// ---------------- chunked selective scan, thread-per-(b,c,e) --------------
__global__ void __launch_bounds__(256) scan_pass1(
        const float* __restrict__ dt,
        const float* __restrict__ u,
        const float* __restrict__ xdbl,
        const float* __restrict__ A_log,
        float* __restrict__ hloc,
        float* __restrict__ ssum) {
    const int e = blockIdx.x * 256 + threadIdx.x;
    const int c = blockIdx.y, b = blockIdx.z;
    __shared__ float4 sB[CLEN][NSTATE/4];
    const int t0 = b * SEQ + c * CLEN;
    for (int i = threadIdx.x; i < CLEN * NSTATE / 4; i += 256) {
        int l = i / (NSTATE/4), q = i % (NSTATE/4);
        sB[l][q] = *(const float4*)&xdbl[(size_t)(t0 + l) * XDBL + RRANK + q * 4];
    }
    __syncthreads();
    float Aen[NSTATE];
    #pragma unroll
    for (int q = 0; q < 4; q++) {
        float4 a = *(const float4*)&A_log[e * NSTATE + q * 4];
        Aen[q*4+0] = -__expf(a.x); Aen[q*4+1] = -__expf(a.y);
        Aen[q*4+2] = -__expf(a.z); Aen[q*4+3] = -__expf(a.w);
    }
    float h[NSTATE];
    #pragma unroll
    for (int n = 0; n < NSTATE; n++) h[n] = 0.f;
    float s = 0.f;
    for (int l = 0; l < CLEN; l++) {
        int t = t0 + l;
        float dtv = dt[(size_t)t * EDIM + e];
        float uv  = u [(size_t)t * EDIM + e];
        s += dtv;
        float du = dtv * uv;
        #pragma unroll
        for (int q = 0; q < 4; q++) {
            float4 Bv = sB[l][q];
            h[q*4+0] = fmaf(h[q*4+0], __expf(dtv * Aen[q*4+0]), du * Bv.x);
            h[q*4+1] = fmaf(h[q*4+1], __expf(dtv * Aen[q*4+1]), du * Bv.y);
            h[q*4+2] = fmaf(h[q*4+2], __expf(dtv * Aen[q*4+2]), du * Bv.z);
            h[q*4+3] = fmaf(h[q*4+3], __expf(dtv * Aen[q*4+3]), du * Bv.w);
        }
    }
    size_t g = ((size_t)(b * EDIM + e) * NCHUNK + c);
    #pragma unroll
    for (int q = 0; q < 4; q++)
        *(float4*)&hloc[g * NSTATE + q * 4] =
            make_float4(h[q*4+0], h[q*4+1], h[q*4+2], h[q*4+3]);
    ssum[g] = s;
}

__global__ void scan_pass2(const float* __restrict__ A_log,
                           const float* __restrict__ ssum,
                           const float* __restrict__ hloc,
                           float* __restrict__ hstart) {
    int i = blockIdx.x * 256 + threadIdx.x;
    int n = i & 15;
    int e = (i >> 4) & (EDIM - 1);
    int b = i >> 15;
    float Aen = -__expf(A_log[e * NSTATE + n]);
    float h = 0.f;
    int gbase = (b * EDIM + e) * NCHUNK;
    for (int c = 0; c < NCHUNK; c++) {
        int g = gbase + c;
        hstart[(size_t)g * NSTATE + n] = h;
        h = fmaf(h, __expf(Aen * ssum[g]), hloc[(size_t)g * NSTATE + n]);
    }
}

__global__ void __launch_bounds__(256) scan_pass3(
        const float* __restrict__ dt,
        const float* __restrict__ u,
        const float* __restrict__ xz,
        const float* __restrict__ xdbl,
        const float* __restrict__ A_log,
        const float* __restrict__ Dp,
        const float* __restrict__ hstart,
        __half* __restrict__ yh,
        __half* __restrict__ yl) {
    const int e = blockIdx.x * 256 + threadIdx.x;
    const int c = blockIdx.y, b = blockIdx.z;
    __shared__ float4 sB[CLEN][NSTATE/4];
    __shared__ float4 sC[CLEN][NSTATE/4];
    const int t0 = b * SEQ + c * CLEN;
    for (int i = threadIdx.x; i < CLEN * NSTATE / 4; i += 256) {
        int l = i / (NSTATE/4), q = i % (NSTATE/4);
        sB[l][q] = *(const float4*)&xdbl[(size_t)(t0 + l) * XDBL + RRANK + q * 4];
        sC[l][q] = *(const float4*)&xdbl[(size_t)(t0 + l) * XDBL + RRANK + NSTATE + q * 4];
    }
    __syncthreads();
    float Aen[NSTATE];
    #pragma unroll
    for (int q = 0; q < 4; q++) {
        float4 a = *(const float4*)&A_log[e * NSTATE + q * 4];
        Aen[q*4+0] = -__expf(a.x); Aen[q*4+1] = -__expf(a.y);
        Aen[q*4+2] = -__expf(a.z); Aen[q*4+3] = -__expf(a.w);
    }
    const float Dv = Dp[e];
    size_t g = ((size_t)(b * EDIM + e) * NCHUNK + c);
    float h[NSTATE];
    #pragma unroll
    for (int q = 0; q < 4; q++) {
        float4 v = *(const float4*)&hstart[g * NSTATE + q * 4];
        h[q*4+0] = v.x; h[q*4+1] = v.y; h[q*4+2] = v.z; h[q*4+3] = v.w;
    }
    for (int l = 0; l < CLEN; l++) {
        int t = t0 + l;
        float dtv = dt[(size_t)t * EDIM + e];
        float uv  = u [(size_t)t * EDIM + e];
        float du = dtv * uv;
        float p = 0.f;
        #pragma unroll
        for (int q = 0; q < 4; q++) {
            float4 Bv = sB[l][q];
            float4 Cv = sC[l][q];
            h[q*4+0] = fmaf(h[q*4+0], __expf(dtv * Aen[q*4+0]), du * Bv.x);
            h[q*4+1] = fmaf(h[q*4+1], __expf(dtv * Aen[q*4+1]), du * Bv.y);
            h[q*4+2] = fmaf(h[q*4+2], __expf(dtv * Aen[q*4+2]), du * Bv.z);
            h[q*4+3] = fmaf(h[q*4+3], __expf(dtv * Aen[q*4+3]), du * Bv.w);
            p = fmaf(h[q*4+0], Cv.x, p);
            p = fmaf(h[q*4+1], Cv.y, p);
            p = fmaf(h[q*4+2], Cv.z, p);
            p = fmaf(h[q*4+3], Cv.w, p);
        }
        float zv = xz[(size_t)t * (2 * EDIM) + EDIM + e];
        float sz = zv / (1.f + __expf(-zv));
        float yv = (p + uv * Dv) * sz;
        __half hb = __float2half(yv);
        yh[(size_t)t * EDIM + e] = hb;
        yl[(size_t)t * EDIM + e] = __float2half(yv - __half2float(hb));
    }
}

// ---------------- launch ----------------
extern "C" void kernel_launch(void* const* d_in, const int* in_sizes, int n_in,
                              void* d_out, int out_size) {
    const float* x         = (const float*)d_in[0];
    const float* norm_w    = (const float*)d_in[1];
    const float* in_proj_w = (const float*)d_in[2];
    const float* conv_w    = (const float*)d_in[3];
    const float* conv_b    = (const float*)d_in[4];
    const float* x_proj_w  = (const float*)d_in[5];
    const float* dt_proj_w = (const float*)d_in[6];
    const float* dt_proj_b = (const float*)d_in[7];
    const float* A_log     = (const float*)d_in[8];
    const float* Dp        = (const float*)d_in[9];
    const float* out_proj_w= (const float*)d_in[10];
    float* out = (float*)d_out;

    float *p_xz, *p_uc, *p_xdbl, *p_dt, *p_hloc, *p_hstart, *p_ssum;
    cudaGetSymbolAddress((void**)&p_xz,    g_xz);
    cudaGetSymbolAddress((void**)&p_uc,    g_uc);
    cudaGetSymbolAddress((void**)&p_xdbl,  g_xdbl);
    cudaGetSymbolAddress((void**)&p_dt,    g_dt);
    cudaGetSymbolAddress((void**)&p_hloc,  g_hloc);
    cudaGetSymbolAddress((void**)&p_hstart,g_hstart);
    cudaGetSymbolAddress((void**)&p_ssum,  g_ssum);
    __half *p_xnh, *p_xnl, *p_wih, *p_uh, *p_ul, *p_xpw;
    __half *p_dtlh, *p_dtll, *p_dtw, *p_yh, *p_yl, *p_woh;
    cudaGetSymbolAddress((void**)&p_xnh,  g_xnh);
    cudaGetSymbolAddress((void**)&p_xnl,  g_xnl);
    cudaGetSymbolAddress((void**)&p_wih,  g_wih);
    cudaGetSymbolAddress((void**)&p_uh,   g_uh);
    cudaGetSymbolAddress((void**)&p_ul,   g_ul);
    cudaGetSymbolAddress((void**)&p_xpw,  g_xpw);
    cudaGetSymbolAddress((void**)&p_dtlh, g_dtlh);
    cudaGetSymbolAddress((void**)&p_dtll, g_dtll);
    cudaGetSymbolAddress((void**)&p_dtw,  g_dtw);
    cudaGetSymbolAddress((void**)&p_yh,   g_yh);
    cudaGetSymbolAddress((void**)&p_yl,   g_yl);
    cudaGetSymbolAddress((void**)&p_woh,  g_woh);

    const int SMEM_128 = NSTAGE * (2*ABUF + 128*ROWB);  // 73728
    const int SMEM_96  = NSTAGE * (2*ABUF + 96*ROWB);   // 67584
    cudaFuncSetAttribute(gemm_f16x2<4,0>, cudaFuncAttributeMaxDynamicSharedMemorySize, SMEM_128);
    cudaFuncSetAttribute(gemm_f16x2<4,1>, cudaFuncAttributeMaxDynamicSharedMemorySize, SMEM_128);
    cudaFuncSetAttribute(gemm_f16x2<4,2>, cudaFuncAttributeMaxDynamicSharedMemorySize, SMEM_128);
    cudaFuncSetAttribute(gemm_f16x2<3,3>, cudaFuncAttributeMaxDynamicSharedMemorySize, SMEM_96);

    // 1. RMSNorm fused with fp16 split
    rmsnorm_split_kernel<<<TOK, 256>>>(x, norm_w, p_xnh, p_xnl);

    // 2. weight converts
    cvt_h_kernel<<<(2*EDIM*DM + 255)/256, 256>>>(in_proj_w, p_wih, 2*EDIM*DM);
    cvt_h_kernel<<<(DM*EDIM + 255)/256, 256>>>(out_proj_w, p_woh, DM*EDIM);
    cvt_h_kernel<<<(XDBL*EDIM + 255)/256, 256>>>(x_proj_w, p_xpw, XDBL*EDIM);
    cvt_h_kernel<<<(EDIM*RRANK + 255)/256, 256>>>(dt_proj_w, p_dtw, EDIM*RRANK);

    // 3. in_proj: [4096,1024] -> [4096,4096]
    gemm_f16x2<4,0><<<dim3(2*EDIM/128, TOK/128), 256, SMEM_128>>>(
        p_xnh, p_xnl, p_wih, p_xz, DM, 2*EDIM, nullptr, nullptr, nullptr, nullptr);

    // 4. conv + SiLU (+ fp16 split of u)
    conv_silu_kernel<<<(TOK*EDIM)/256, 256>>>(p_xz, conv_w, conv_b, p_uc, p_uh, p_ul);

    // 5. x_proj: [4096,2048] @ [96,2048]^T -> [4096,96] (+ fp16 dt_low aux)
    gemm_f16x2<3,3><<<dim3(1, TOK/128), 192, SMEM_96>>>(
        p_uh, p_ul, p_xpw, p_xdbl, EDIM, XDBL, nullptr, nullptr, p_dtlh, p_dtll);

    // 6. dt_proj + bias + softplus: [4096,64] @ [2048,64]^T -> [4096,2048]
    gemm_f16x2<4,1><<<dim3(EDIM/128, TOK/128), 256, SMEM_128>>>(
        p_dtlh, p_dtll, p_dtw, p_dt, RRANK, EDIM, dt_proj_b, nullptr, nullptr, nullptr);

    // 7-9. chunked selective scan (+ D skip + z gate + fp16 split)
    scan_pass1<<<dim3(EDIM/256, NCHUNK, BATCH), 256>>>(
        p_dt, p_uc, p_xdbl, A_log, p_hloc, p_ssum);
    scan_pass2<<<BATCH*EDIM*NSTATE/256, 256>>>(A_log, p_ssum, p_hloc, p_hstart);
    scan_pass3<<<dim3(EDIM/256, NCHUNK, BATCH), 256>>>(
        p_dt, p_uc, p_xz, p_xdbl, A_log, Dp, p_hstart, p_yh, p_yl);

    // 10. out_proj + residual
    gemm_f16x2<4,2><<<dim3(DM/128, TOK/128), 256, SMEM_128>>>(
        p_yh, p_yl, p_woh, out, EDIM, DM, nullptr, x, nullptr, nullptr);
}